// round 13
// baseline (speedup 1.0000x reference)
#include <cuda_runtime.h>
#include <cuda_bf16.h>
#include <cstdint>

// ---------------------------------------------------------------------------
// L=256, B=32, D_MODEL=512, N_HEAD=8, D_HEAD=64, 2m=512
// All GEMM-shaped work on mma.sync m16n8k16 bf16; cp.async ping-pong;
// ldmatrix fragment loads; attn4 cross-sc pipelined (R13).
// Device globals only bound in device code (GB300/ATS pitfall).
// ---------------------------------------------------------------------------
#define ROWS 8192
#define BH 256

__device__ __nv_bfloat16  g_qkvb[ROWS * 2048];       // qkv output bf16
__device__ __nv_bfloat16  g_hb [ROWS * 512];         // h in bf16
__device__ __nv_bfloat16  g_wqkvT[2048 * 512];       // wqkv^T bf16 [N,K]
__device__ __nv_bfloat16  g_woT [512 * 512];         // wo^T bf16 [N,K]
__device__ __nv_bfloat16  g_pT  [256 * 64];          // (C*proj)^T bf16 [m][d]
__device__ __nv_bfloat16  g_qf_b[BH * 256 * 512];    // features bf16
__device__ __nv_bfloat16  g_kf_b[BH * 256 * 512];
__device__ __nv_bfloat16  g_vt [BH * 64 * 256];      // V^T bf16 [bh*64+d][l]
__device__ __nv_bfloat16  g_ai_b[ROWS * 512];        // attn out bf16
__device__ __nv_bfloat16  g_yb [ROWS * 512];         // w_o GEMM result bf16

// ------------------------- helpers ------------------------------------------
__device__ __forceinline__ void mma16816(float c[4],
    uint32_t a0, uint32_t a1, uint32_t a2, uint32_t a3,
    uint32_t b0, uint32_t b1)
{
    asm volatile(
        "mma.sync.aligned.m16n8k16.row.col.f32.bf16.bf16.f32 "
        "{%0,%1,%2,%3}, {%4,%5,%6,%7}, {%8,%9}, {%0,%1,%2,%3};"
        : "+f"(c[0]), "+f"(c[1]), "+f"(c[2]), "+f"(c[3])
        : "r"(a0), "r"(a1), "r"(a2), "r"(a3), "r"(b0), "r"(b1));
}
__device__ __forceinline__ void ldsm4(uint32_t* r, uint32_t addr) {
    asm volatile("ldmatrix.sync.aligned.m8n8.x4.shared.b16 {%0,%1,%2,%3}, [%4];"
        : "=r"(r[0]), "=r"(r[1]), "=r"(r[2]), "=r"(r[3]) : "r"(addr));
}
__device__ __forceinline__ uint32_t pk2(float a, float b) {
    __nv_bfloat162 t = __floats2bfloat162_rn(a, b);
    return *(uint32_t*)&t;
}
__device__ __forceinline__ uint32_t smem_u32(const void* p) {
    uint32_t a;
    asm("{ .reg .u64 t; cvta.to.shared.u64 t, %1; cvt.u32.u64 %0, t; }"
        : "=r"(a) : "l"(p));
    return a;
}
__device__ __forceinline__ void cpa16(uint32_t saddr, const void* g) {
    asm volatile("cp.async.cg.shared.global [%0], [%1], 16;"
                 :: "r"(saddr), "l"(g) : "memory");
}
#define CP_COMMIT() asm volatile("cp.async.commit_group;" ::: "memory")
#define CP_WAIT0()  asm volatile("cp.async.wait_group 0;" ::: "memory")

template<int NW>
__device__ __forceinline__ float block_sum(float v, float* red) {
    #pragma unroll
    for (int o = 16; o; o >>= 1) v += __shfl_xor_sync(0xffffffffu, v, o);
    if ((threadIdx.x & 31) == 0) red[threadIdx.x >> 5] = v;
    __syncthreads();
    if (threadIdx.x < 32) {
        float t = (threadIdx.x < NW) ? red[threadIdx.x] : 0.f;
        #pragma unroll
        for (int o = 16; o; o >>= 1) t += __shfl_xor_sync(0xffffffffu, t, o);
        if (threadIdx.x == 0) red[0] = t;
    }
    __syncthreads();
    float r = red[0];
    __syncthreads();
    return r;
}

// ------------------------- merged prep kernel -------------------------------
__device__ __forceinline__ void transpose_dev(
    const float* __restrict__ src, __nv_bfloat16* __restrict__ dst,
    int K, int N, int bx, int by, int tx, int ty, float (*t)[33])
{
    int bn = bx * 32, bk = by * 32;
    #pragma unroll
    for (int i = ty; i < 32; i += 8)
        t[i][tx] = src[(size_t)(bk + i) * N + bn + tx];
    __syncthreads();
    #pragma unroll
    for (int i = ty; i < 32; i += 8)
        dst[(size_t)(bn + i) * K + bk + tx] = __float2bfloat16(t[tx][i]);
}

__global__ __launch_bounds__(256) void prep_all(
    const float* __restrict__ h, const float* __restrict__ wqkv,
    const float* __restrict__ wo, const float* __restrict__ proj)
{
    __shared__ float tbuf[32][33];
    int blk = blockIdx.x, tid = threadIdx.x;
    int tx = tid & 31, ty = tid >> 5;
    if (blk < 4096) {                       // conv_h
        int i = blk * 256 + tid;
        float4 v = ((const float4*)h)[i];
        struct alignas(8) BF4 { __nv_bfloat162 a, b; };
        BF4 pk;
        pk.a = __floats2bfloat162_rn(v.x, v.y);
        pk.b = __floats2bfloat162_rn(v.z, v.w);
        ((BF4*)g_hb)[i] = pk;
    } else if (blk < 5120) {                // trans_wqkv: 64 x 16
        int idx = blk - 4096;
        transpose_dev(wqkv, g_wqkvT, 512, 2048, idx & 63, idx >> 6, tx, ty, tbuf);
    } else if (blk < 5376) {                // trans_wo: 16 x 16
        int idx = blk - 5120;
        transpose_dev(wo, g_woT, 512, 512, idx & 15, idx >> 4, tx, ty, tbuf);
    } else {                                // prep_pT
        int i = (blk - 5376) * 256 + tid;
        int d = i >> 8, m = i & 255;
        g_pT[m * 64 + d] = __float2bfloat16(proj[i] * 0.3535533905932738f);
    }
}

// ------------------------- bf16 tensor-core GEMM (cp.async + ldmatrix) ------
#define GPAD 36
#define GEMM_SMEM (2 * 9216 * 4)     // 73,728 B

#define GEMM_PREFETCH(p, buf) do {                                             \
    int _b = (buf) * 9216;                                                     \
    _Pragma("unroll")                                                          \
    for (int _j = 0; _j < 4; _j++) {                                           \
        int _i = tid + _j * 256; int _r = _i >> 3, _c = (_i & 7) * 4;          \
        cpa16(sbase + (uint32_t)(_b + _r * GPAD + _c) * 4,                     \
              A32 + (size_t)(bm + _r) * 256 + (p) * 32 + _c);                  \
        cpa16(sbase + (uint32_t)(_b + 4608 + _r * GPAD + _c) * 4,              \
              B32 + (size_t)(bn + _r) * 256 + (p) * 32 + _c);                  \
    }                                                                          \
} while (0)

template<bool BF16OUT>
__device__ __forceinline__ void gemm_body(
    const __nv_bfloat16* __restrict__ A, const __nv_bfloat16* __restrict__ B,
    float* __restrict__ C, uint32_t* __restrict__ Cb, int Ntot)
{
    extern __shared__ uint32_t sw[];
    uint32_t sbase = smem_u32(sw);
    int tid = threadIdx.x, wid = tid >> 5, lane = tid & 31;
    int wm = wid >> 2, wn = wid & 3;
    int g = lane >> 2, t = lane & 3;
    int bm = blockIdx.y * 128, bn = blockIdx.x * 128;
    const uint32_t* A32 = (const uint32_t*)A;
    const uint32_t* B32 = (const uint32_t*)B;

    int arow = wm * 64 + (lane & 15);
    int akof = (lane >> 4) << 2;
    int brow = wn * 32 + ((lane >> 4) & 1) * 8 + (lane & 7);
    int bkof = ((lane >> 3) & 1) << 2;

    float acc[4][4][4];
    #pragma unroll
    for (int i = 0; i < 4; i++)
        #pragma unroll
        for (int j = 0; j < 4; j++)
            #pragma unroll
            for (int q = 0; q < 4; q++) acc[i][j][q] = 0.f;

    GEMM_PREFETCH(0, 0);
    CP_COMMIT();

    for (int p = 0; p < 8; p++) {
        CP_WAIT0();
        __syncthreads();
        if (p < 7) { GEMM_PREFETCH(p + 1, (p + 1) & 1); CP_COMMIT(); }
        uint32_t ab = sbase + (uint32_t)((p & 1) * 9216) * 4;
        uint32_t bb = ab + 4608 * 4;
        #pragma unroll
        for (int kk = 0; kk < 4; kk++) {
            uint32_t af[4][4], bf[2][4];
            #pragma unroll
            for (int i = 0; i < 4; i++)
                ldsm4(af[i], ab + (uint32_t)((arow + i * 16) * GPAD + kk * 8 + akof) * 4);
            #pragma unroll
            for (int jj = 0; jj < 2; jj++)
                ldsm4(bf[jj], bb + (uint32_t)((brow + jj * 16) * GPAD + kk * 8 + bkof) * 4);
            #pragma unroll
            for (int i = 0; i < 4; i++)
                #pragma unroll
                for (int j = 0; j < 4; j++)
                    mma16816(acc[i][j], af[i][0], af[i][1], af[i][2], af[i][3],
                             bf[j >> 1][(j & 1) * 2], bf[j >> 1][(j & 1) * 2 + 1]);
        }
    }
    #pragma unroll
    for (int i = 0; i < 4; i++) {
        int row = bm + wm * 64 + i * 16 + g;
        #pragma unroll
        for (int j = 0; j < 4; j++) {
            if (BF16OUT) {
                int widx = (bn >> 1) + wn * 16 + j * 4 + t;
                Cb[(size_t)row * (Ntot >> 1) + widx] = pk2(acc[i][j][0], acc[i][j][1]);
                Cb[(size_t)(row + 8) * (Ntot >> 1) + widx] = pk2(acc[i][j][2], acc[i][j][3]);
            } else {
                int col = bn + wn * 32 + j * 8 + t * 2;
                *(float2*)&C[(size_t)row * Ntot + col] =
                    make_float2(acc[i][j][0], acc[i][j][1]);
                *(float2*)&C[(size_t)(row + 8) * Ntot + col] =
                    make_float2(acc[i][j][2], acc[i][j][3]);
            }
        }
    }
}
__global__ __launch_bounds__(256) void gemm_qkv() {
    gemm_body<true>(g_hb, g_wqkvT, nullptr, (uint32_t*)g_qkvb, 2048);
}
__global__ __launch_bounds__(256) void gemm_wo() {
    gemm_body<true>(g_ai_b, g_woT, nullptr, (uint32_t*)g_yb, 512);
}

// ------------------------- feat2: FAVOR+ via tensor cores -------------------
#define F_P 0
#define F_X 9216
#define F_V 16128
#define F_STG 18432
#define F_SS 26880
#define FEAT2_SMEM (27392 * 4)     // 109,568 B

__global__ __launch_bounds__(256) void feat2(
    const float* __restrict__ pi0, const float* __restrict__ pi1)
{
    extern __shared__ uint32_t fw[];
    __nv_bfloat16* Vh = (__nv_bfloat16*)(fw + F_V);   // l*72 + d
    float* ss = (float*)(fw + F_SS);
    int tid = threadIdx.x, wid = tid >> 5, lane = tid & 31;
    int wm = wid >> 2, wn = wid & 3;
    int g = lane >> 2, t = lane & 3;
    int l0 = blockIdx.x * 64, bh = blockIdx.y;
    int hh = bh & 7, b = bh >> 3;

    const uint32_t* pTw = (const uint32_t*)g_pT;
    #pragma unroll
    for (int w = 0; w < 32; w++) {
        int idx = tid + w * 256;
        int m = idx >> 5, wd = idx & 31;
        fw[F_P + m * 36 + wd] = pTw[m * 32 + wd];
    }
    const uint32_t* Xg = (const uint32_t*)g_qkvb;
    const __nv_bfloat162 c07 = __float2bfloat162_rn(0.7f);
    #pragma unroll
    for (int w = 0; w < 32; w++) {
        int idx = tid + w * 256;
        int r = idx >> 7, wc = idx & 127;
        uint32_t word = Xg[(size_t)((l0 + r) * 32 + b) * 1024 + hh * 128 + wc];
        if (wc < 96) {
            int seg = wc >> 5, cc = wc & 31;
            if (seg == 2) {
                __nv_bfloat162 tt = *(__nv_bfloat162*)&word;
                tt = __hmul2(tt, c07);
                word = *(uint32_t*)&tt;
            }
            fw[F_X + seg * 2304 + r * 36 + cc] = word;
        } else {
            fw[F_V + r * 36 + (wc - 96)] = word;
        }
    }
    __syncthreads();

    #pragma unroll
    for (int w = 0; w < 16; w++) {
        int idx = tid + w * 256;
        int d = idx >> 6, l = idx & 63;
        g_vt[(size_t)(bh * 64 + d) * 256 + l0 + l] = Vh[l * 72 + d];
    }

    // ===================== seg0: q features =====================
    {
        float acc[2][8][4];
        #pragma unroll
        for (int i = 0; i < 2; i++)
            #pragma unroll
            for (int j = 0; j < 8; j++)
                #pragma unroll
                for (int q = 0; q < 4; q++) acc[i][j][q] = 0.f;
        #pragma unroll
        for (int kk = 0; kk < 4; kk++) {
            uint32_t af[2][4], bf[8][2];
            #pragma unroll
            for (int i = 0; i < 2; i++) {
                int r0 = wm * 32 + i * 16;
                af[i][0] = fw[F_X + (r0 + g    ) * 36 + kk * 8 + t];
                af[i][1] = fw[F_X + (r0 + g + 8) * 36 + kk * 8 + t];
                af[i][2] = fw[F_X + (r0 + g    ) * 36 + kk * 8 + t + 4];
                af[i][3] = fw[F_X + (r0 + g + 8) * 36 + kk * 8 + t + 4];
            }
            #pragma unroll
            for (int j = 0; j < 8; j++) {
                int n0 = wn * 64 + j * 8;
                bf[j][0] = fw[F_P + (n0 + g) * 36 + kk * 8 + t];
                bf[j][1] = fw[F_P + (n0 + g) * 36 + kk * 8 + t + 4];
            }
            #pragma unroll
            for (int i = 0; i < 2; i++)
                #pragma unroll
                for (int j = 0; j < 8; j++)
                    mma16816(acc[i][j], af[i][0], af[i][1], af[i][2], af[i][3],
                             bf[j][0], bf[j][1]);
        }
        float pr[2][2] = {{0.f, 0.f}, {0.f, 0.f}};
        #pragma unroll
        for (int i = 0; i < 2; i++)
            #pragma unroll
            for (int j = 0; j < 8; j++)
                #pragma unroll
                for (int q = 0; q < 4; q++) {
                    float v = fminf(fmaxf(acc[i][j][q], -30.f), 30.f);
                    float e = __expf(v);
                    acc[i][j][q] = e;
                    pr[i][q >> 1] += e + __fdividef(1.f, e);
                }
        #pragma unroll
        for (int i = 0; i < 2; i++)
            #pragma unroll
            for (int hf = 0; hf < 2; hf++) {
                pr[i][hf] += __shfl_xor_sync(0xffffffffu, pr[i][hf], 1);
                pr[i][hf] += __shfl_xor_sync(0xffffffffu, pr[i][hf], 2);
            }
        if (t == 0) {
            #pragma unroll
            for (int i = 0; i < 2; i++) {
                ss[(wm * 32 + i * 16 + g    ) * 4 + wn] = pr[i][0];
                ss[(wm * 32 + i * 16 + g + 8) * 4 + wn] = pr[i][1];
            }
        }
        __syncthreads();
        float invp[2][2];
        #pragma unroll
        for (int i = 0; i < 2; i++)
            #pragma unroll
            for (int hf = 0; hf < 2; hf++) {
                int r = wm * 32 + i * 16 + g + hf * 8;
                float s = ss[r * 4] + ss[r * 4 + 1] + ss[r * 4 + 2] + ss[r * 4 + 3];
                invp[i][hf] = __fdividef(1.f, s);
            }
        uint32_t* dstw = (uint32_t*)g_qf_b;
        #pragma unroll
        for (int i = 0; i < 2; i++) {
            int sr = wm * 32 + i * 16;
            #pragma unroll
            for (int j = 0; j < 8; j++) {
                int wc = wn * 32 + j * 4 + t;
                fw[F_STG + (sr + g    ) * 132 + wc] =
                    pk2(acc[i][j][0] * invp[i][0], acc[i][j][1] * invp[i][0]);
                fw[F_STG + (sr + g + 8) * 132 + wc] =
                    pk2(acc[i][j][2] * invp[i][1], acc[i][j][3] * invp[i][1]);
            }
        }
        __syncthreads();
        #pragma unroll
        for (int w = 0; w < 32; w++) {
            int idx = tid + w * 256;
            int r = idx >> 7, wd = idx & 127;
            dstw[(size_t)(bh * 256 + l0 + r) * 256 + wd] = fw[F_STG + r * 132 + wd];
        }
        __syncthreads();
        #pragma unroll
        for (int i = 0; i < 2; i++) {
            int sr = wm * 32 + i * 16;
            #pragma unroll
            for (int j = 0; j < 8; j++) {
                int wc = wn * 32 + j * 4 + t;
                fw[F_STG + (sr + g    ) * 132 + wc] =
                    pk2(__fdividef(invp[i][0], acc[i][j][0]),
                        __fdividef(invp[i][0], acc[i][j][1]));
                fw[F_STG + (sr + g + 8) * 132 + wc] =
                    pk2(__fdividef(invp[i][1], acc[i][j][2]),
                        __fdividef(invp[i][1], acc[i][j][3]));
            }
        }
        __syncthreads();
        #pragma unroll
        for (int w = 0; w < 32; w++) {
            int idx = tid + w * 256;
            int r = idx >> 7, wd = idx & 127;
            dstw[(size_t)(bh * 256 + l0 + r) * 256 + 128 + wd] = fw[F_STG + r * 132 + wd];
        }
        __syncthreads();
    }

    // ===================== fused seg1+seg2: k features =====================
    {
        float a1[2][8][4], a2[2][8][4];
        #pragma unroll
        for (int i = 0; i < 2; i++)
            #pragma unroll
            for (int j = 0; j < 8; j++)
                #pragma unroll
                for (int q = 0; q < 4; q++) { a1[i][j][q] = 0.f; a2[i][j][q] = 0.f; }
        #pragma unroll
        for (int kk = 0; kk < 4; kk++) {
            uint32_t af1[2][4], af2[2][4], bf[8][2];
            #pragma unroll
            for (int i = 0; i < 2; i++) {
                int r0 = wm * 32 + i * 16;
                af1[i][0] = fw[F_X + 2304 + (r0 + g    ) * 36 + kk * 8 + t];
                af1[i][1] = fw[F_X + 2304 + (r0 + g + 8) * 36 + kk * 8 + t];
                af1[i][2] = fw[F_X + 2304 + (r0 + g    ) * 36 + kk * 8 + t + 4];
                af1[i][3] = fw[F_X + 2304 + (r0 + g + 8) * 36 + kk * 8 + t + 4];
                af2[i][0] = fw[F_X + 4608 + (r0 + g    ) * 36 + kk * 8 + t];
                af2[i][1] = fw[F_X + 4608 + (r0 + g + 8) * 36 + kk * 8 + t];
                af2[i][2] = fw[F_X + 4608 + (r0 + g    ) * 36 + kk * 8 + t + 4];
                af2[i][3] = fw[F_X + 4608 + (r0 + g + 8) * 36 + kk * 8 + t + 4];
            }
            #pragma unroll
            for (int j = 0; j < 8; j++) {
                int n0 = wn * 64 + j * 8;
                bf[j][0] = fw[F_P + (n0 + g) * 36 + kk * 8 + t];
                bf[j][1] = fw[F_P + (n0 + g) * 36 + kk * 8 + t + 4];
            }
            #pragma unroll
            for (int i = 0; i < 2; i++)
                #pragma unroll
                for (int j = 0; j < 8; j++) {
                    mma16816(a1[i][j], af1[i][0], af1[i][1], af1[i][2], af1[i][3],
                             bf[j][0], bf[j][1]);
                    mma16816(a2[i][j], af2[i][0], af2[i][1], af2[i][2], af2[i][3],
                             bf[j][0], bf[j][1]);
                }
        }
        float pr1[2][2] = {{0.f, 0.f}, {0.f, 0.f}};
        float pr2[2][2] = {{0.f, 0.f}, {0.f, 0.f}};
        #pragma unroll
        for (int i = 0; i < 2; i++)
            #pragma unroll
            for (int j = 0; j < 8; j++)
                #pragma unroll
                for (int q = 0; q < 4; q++) {
                    float v1 = fminf(fmaxf(a1[i][j][q], -30.f), 30.f);
                    float e1 = __expf(v1);
                    a1[i][j][q] = e1;
                    pr1[i][q >> 1] += e1 + __fdividef(1.f, e1);
                    float v2 = fminf(fmaxf(a2[i][j][q], -30.f), 30.f);
                    float e2 = __expf(v2);
                    a2[i][j][q] = e2;
                    pr2[i][q >> 1] += e2 + __fdividef(1.f, e2);
                }
        #pragma unroll
        for (int i = 0; i < 2; i++)
            #pragma unroll
            for (int hf = 0; hf < 2; hf++) {
                pr1[i][hf] += __shfl_xor_sync(0xffffffffu, pr1[i][hf], 1);
                pr1[i][hf] += __shfl_xor_sync(0xffffffffu, pr1[i][hf], 2);
                pr2[i][hf] += __shfl_xor_sync(0xffffffffu, pr2[i][hf], 1);
                pr2[i][hf] += __shfl_xor_sync(0xffffffffu, pr2[i][hf], 2);
            }
        if (t == 0) {
            #pragma unroll
            for (int i = 0; i < 2; i++) {
                int ra = wm * 32 + i * 16 + g, rb = ra + 8;
                ss[ra * 4 + wn]       = pr1[i][0];
                ss[rb * 4 + wn]       = pr1[i][1];
                ss[256 + ra * 4 + wn] = pr2[i][0];
                ss[256 + rb * 4 + wn] = pr2[i][1];
            }
        }
        __syncthreads();
        float iv1[2][2], iv2[2][2];
        #pragma unroll
        for (int i = 0; i < 2; i++)
            #pragma unroll
            for (int hf = 0; hf < 2; hf++) {
                int r = wm * 32 + i * 16 + g + hf * 8;
                float s1 = ss[r * 4] + ss[r * 4 + 1] + ss[r * 4 + 2] + ss[r * 4 + 3];
                float s2 = ss[256 + r * 4] + ss[256 + r * 4 + 1]
                         + ss[256 + r * 4 + 2] + ss[256 + r * 4 + 3];
                iv1[i][hf] = __fdividef(pi0[hh * 256 + l0 + r], s1);
                iv2[i][hf] = __fdividef(pi1[hh * 256 + l0 + r], s2);
            }
        uint32_t* dstw = (uint32_t*)g_kf_b;
        #pragma unroll
        for (int i = 0; i < 2; i++) {
            int sr = wm * 32 + i * 16;
            #pragma unroll
            for (int j = 0; j < 8; j++) {
                int wc = wn * 32 + j * 4 + t;
                fw[F_STG + (sr + g    ) * 132 + wc] =
                    pk2(a1[i][j][0] * iv1[i][0] + a2[i][j][0] * iv2[i][0],
                        a1[i][j][1] * iv1[i][0] + a2[i][j][1] * iv2[i][0]);
                fw[F_STG + (sr + g + 8) * 132 + wc] =
                    pk2(a1[i][j][2] * iv1[i][1] + a2[i][j][2] * iv2[i][1],
                        a1[i][j][3] * iv1[i][1] + a2[i][j][3] * iv2[i][1]);
            }
        }
        __syncthreads();
        #pragma unroll
        for (int w = 0; w < 32; w++) {
            int idx = tid + w * 256;
            int r = idx >> 7, wd = idx & 127;
            dstw[(size_t)(bh * 256 + l0 + r) * 256 + wd] = fw[F_STG + r * 132 + wd];
        }
        __syncthreads();
        #pragma unroll
        for (int i = 0; i < 2; i++) {
            int sr = wm * 32 + i * 16;
            #pragma unroll
            for (int j = 0; j < 8; j++) {
                int wc = wn * 32 + j * 4 + t;
                fw[F_STG + (sr + g    ) * 132 + wc] =
                    pk2(__fdividef(iv1[i][0], a1[i][j][0]) + __fdividef(iv2[i][0], a2[i][j][0]),
                        __fdividef(iv1[i][0], a1[i][j][1]) + __fdividef(iv2[i][0], a2[i][j][1]));
                fw[F_STG + (sr + g + 8) * 132 + wc] =
                    pk2(__fdividef(iv1[i][1], a1[i][j][2]) + __fdividef(iv2[i][1], a2[i][j][2]),
                        __fdividef(iv1[i][1], a1[i][j][3]) + __fdividef(iv2[i][1], a2[i][j][3]));
            }
        }
        __syncthreads();
        #pragma unroll
        for (int w = 0; w < 32; w++) {
            int idx = tid + w * 256;
            int r = idx >> 7, wd = idx & 127;
            dstw[(size_t)(bh * 256 + l0 + r) * 256 + 128 + wd] = fw[F_STG + r * 132 + wd];
        }
    }
}

// ------------------------- attn4: flash, all-mma, cross-sc pipeline ---------
// grid (512): bh = blk>>1, tc = 1-(blk&1) (pair adjacency -> K shares L2).
// Double-buffered V; next-sc V + panel0 prefetched during p==7 so the
// mask/rowsum/PV phase covers those loads.
// smem words: QK bufs 2*9216 | V 2*4352 | ds 128
#define A4_V 18432
#define A4_D 27136
#define ATTN4_SMEM ((27136 + 128) * 4)    // 109,056 B

#define AT_PREF(scv, p, buf) do {                                              \
    int _b = (buf) * 9216;                                                      \
    _Pragma("unroll")                                                           \
    for (int _j = 0; _j < 4; _j++) {                                            \
        int _i = tid + _j * 256; int _r = _i >> 3, _c = (_i & 7) * 4;           \
        cpa16(sbase + (uint32_t)(_b + _r * 36 + _c) * 4,                        \
              Qw + (size_t)(bh * 256 + tc * 128 + _r) * 256 + (p) * 32 + _c);   \
        cpa16(sbase + (uint32_t)(_b + 4608 + _r * 36 + _c) * 4,                 \
              Kw + (size_t)(bh * 256 + (scv) * 128 + _r) * 256 + (p) * 32 + _c);\
    }                                                                           \
} while (0)

#define AT_PREFV(scv, vb) do {                                                  \
    _Pragma("unroll")                                                           \
    for (int _j = 0; _j < 4; _j++) {                                            \
        int _i = tid + _j * 256;                                                \
        int _d = _i >> 4, _wd = (_i & 15) * 4;                                  \
        cpa16(sbase + (uint32_t)(A4_V + (vb) * 4352 + _d * 68 + _wd) * 4,       \
              Vw + (size_t)(bh * 64 + _d) * 128 + (scv) * 64 + _wd);            \
    }                                                                           \
} while (0)

__global__ __launch_bounds__(256) void attn4() {
    extern __shared__ uint32_t aw[];
    uint32_t sbase = smem_u32(aw);
    float* ds = (float*)(aw + A4_D);
    int tid = threadIdx.x, wid = tid >> 5, lane = tid & 31;
    int g = lane >> 2, t = lane & 3;
    int blk = blockIdx.x;
    int bh = blk >> 1;
    int tc = 1 - (blk & 1);
    int hh = bh & 7, b = bh >> 3;
    int lr0 = wid * 16;
    const uint32_t* Qw = (const uint32_t*)g_qf_b;
    const uint32_t* Kw = (const uint32_t*)g_kf_b;
    const uint32_t* Vw = (const uint32_t*)g_vt;

    int alrow = lr0 + (lane & 15);
    int akof  = (lane >> 4) << 2;
    int brow  = ((lane >> 4) & 1) * 8 + (lane & 7);
    int bkof  = ((lane >> 3) & 1) << 2;

    float out[8][4];
    #pragma unroll
    for (int nd = 0; nd < 8; nd++)
        #pragma unroll
        for (int q = 0; q < 4; q++) out[nd][q] = 0.f;
    float dsum0 = 0.f, dsum1 = 0.f;

    // initial loads: V(sc=0) + panel0(sc=0)
    AT_PREFV(0, 0);
    AT_PREF(0, 0, 0);
    CP_COMMIT();

    for (int sc = 0; sc <= tc; sc++) {
        int vb = sc & 1;
        float acc[16][4];
        #pragma unroll
        for (int j = 0; j < 16; j++)
            #pragma unroll
            for (int q = 0; q < 4; q++) acc[j][q] = 0.f;

        for (int p = 0; p < 8; p++) {
            CP_WAIT0();
            __syncthreads();
            if (p < 7) {
                AT_PREF(sc, p + 1, (p + 1) & 1);
                CP_COMMIT();
            } else if (sc < tc) {
                AT_PREFV(sc + 1, vb ^ 1);
                AT_PREF(sc + 1, 0, 0);
                CP_COMMIT();
            }
            uint32_t qb = sbase + (uint32_t)((p & 1) * 9216) * 4;
            uint32_t kb = qb + 4608 * 4;
            #pragma unroll
            for (int kk = 0; kk < 4; kk++) {
                uint32_t aq[4];
                ldsm4(aq, qb + (uint32_t)(alrow * 36 + kk * 8 + akof) * 4);
                #pragma unroll
                for (int jj = 0; jj < 8; jj++) {
                    uint32_t bk[4];
                    ldsm4(bk, kb + (uint32_t)((jj * 16 + brow) * 36 + kk * 8 + bkof) * 4);
                    mma16816(acc[2 * jj],     aq[0], aq[1], aq[2], aq[3], bk[0], bk[1]);
                    mma16816(acc[2 * jj + 1], aq[0], aq[1], aq[2], aq[3], bk[2], bk[3]);
                }
            }
        }
        if (sc == tc) {
            int lr = lr0 + g;
            #pragma unroll
            for (int j = 0; j < 16; j++) {
                int c0 = j * 8 + 2 * t;
                if (c0     > lr)     acc[j][0] = 0.f;
                if (c0 + 1 > lr)     acc[j][1] = 0.f;
                if (c0     > lr + 8) acc[j][2] = 0.f;
                if (c0 + 1 > lr + 8) acc[j][3] = 0.f;
            }
        }
        #pragma unroll
        for (int j = 0; j < 16; j++) {
            dsum0 += acc[j][0] + acc[j][1];
            dsum1 += acc[j][2] + acc[j][3];
        }
        // PV: repack S to bf16 A-fragments, mma vs V^T (ldmatrix for V frags)
        uint32_t vbase = sbase + (uint32_t)(A4_V + vb * 4352) * 4;
        #pragma unroll
        for (int ks = 0; ks < 8; ks++) {
            uint32_t a0 = pk2(acc[2 * ks][0],     acc[2 * ks][1]);
            uint32_t a1 = pk2(acc[2 * ks][2],     acc[2 * ks][3]);
            uint32_t a2 = pk2(acc[2 * ks + 1][0], acc[2 * ks + 1][1]);
            uint32_t a3 = pk2(acc[2 * ks + 1][2], acc[2 * ks + 1][3]);
            #pragma unroll
            for (int nd2 = 0; nd2 < 4; nd2++) {
                uint32_t bv[4];
                ldsm4(bv, vbase + (uint32_t)((nd2 * 16 + brow) * 68 + ks * 8 + bkof) * 4);
                mma16816(out[2 * nd2],     a0, a1, a2, a3, bv[0], bv[1]);
                mma16816(out[2 * nd2 + 1], a0, a1, a2, a3, bv[2], bv[3]);
            }
        }
    }

    dsum0 += __shfl_xor_sync(0xffffffffu, dsum0, 1);
    dsum0 += __shfl_xor_sync(0xffffffffu, dsum0, 2);
    dsum1 += __shfl_xor_sync(0xffffffffu, dsum1, 1);
    dsum1 += __shfl_xor_sync(0xffffffffu, dsum1, 2);
    if (t == 0) { ds[lr0 + g] = dsum0; ds[lr0 + g + 8] = dsum1; }
    __syncthreads();
    int r0 = lr0 + g, r1 = lr0 + g + 8;
    float inv0 = __fdividef(0.125f, ds[r0] + 1e-5f);
    float inv1 = __fdividef(0.125f, ds[r1] + 1e-5f);
    int l0g = tc * 128;
    #pragma unroll
    for (int nd = 0; nd < 8; nd++) {
        int d = nd * 8 + 2 * t;
        __nv_bfloat16* d0 = g_ai_b + (size_t)((l0g + r0) * 32 + b) * 512 + hh * 64 + d;
        __nv_bfloat16* d1 = g_ai_b + (size_t)((l0g + r1) * 32 + b) * 512 + hh * 64 + d;
        *(__nv_bfloat162*)d0 = __floats2bfloat162_rn(out[nd][0] * inv0, out[nd][1] * inv0);
        *(__nv_bfloat162*)d1 = __floats2bfloat162_rn(out[nd][2] * inv1, out[nd][3] * inv1);
    }
}

// ------------------------- residual + LayerNorm ----------------------------
__global__ __launch_bounds__(512) void ln_kernel(
    const float* __restrict__ hin, const float* __restrict__ gamma,
    const float* __restrict__ beta, float* __restrict__ out)
{
    __shared__ float red[32];
    int r = blockIdx.x, j = threadIdx.x;
    float x = __bfloat162float(g_yb[(size_t)r * 512 + j]) + hin[(size_t)r * 512 + j];
    float s1 = block_sum<16>(x, red);
    float mu = s1 * (1.f / 512.f);
    float d = x - mu;
    float s2 = block_sum<16>(d * d, red);
    float rstd = rsqrtf(s2 * (1.f / 512.f) + 1e-5f);
    out[(size_t)r * 512 + j] = d * rstd * gamma[j] + beta[j];
}

// ------------------------- launch ------------------------------------------
extern "C" void kernel_launch(void* const* d_in, const int* in_sizes, int n_in,
                              void* d_out, int out_size) {
    const float* h     = (const float*)d_in[0];
    const float* wqkv  = (const float*)d_in[1];
    const float* wo    = (const float*)d_in[2];
    const float* gamma = (const float*)d_in[3];
    const float* beta  = (const float*)d_in[4];
    const float* pi0   = (const float*)d_in[5];
    const float* pi1   = (const float*)d_in[6];
    const float* proj  = (const float*)d_in[7];

    cudaFuncSetAttribute(gemm_qkv, cudaFuncAttributeMaxDynamicSharedMemorySize, GEMM_SMEM);
    cudaFuncSetAttribute(gemm_wo,  cudaFuncAttributeMaxDynamicSharedMemorySize, GEMM_SMEM);
    cudaFuncSetAttribute(feat2,    cudaFuncAttributeMaxDynamicSharedMemorySize, FEAT2_SMEM);
    cudaFuncSetAttribute(attn4,    cudaFuncAttributeMaxDynamicSharedMemorySize, ATTN4_SMEM);

    prep_all<<<5440, 256>>>(h, wqkv, wo, proj);
    gemm_qkv<<<dim3(16, 64), 256, GEMM_SMEM>>>();
    feat2<<<dim3(4, 256), 256, FEAT2_SMEM>>>(pi0, pi1);
    attn4<<<512, 256, ATTN4_SMEM>>>();
    gemm_wo<<<dim3(4, 64), 256, GEMM_SMEM>>>();
    ln_kernel<<<8192, 512>>>(h, gamma, beta, (float*)d_out);
}

// round 14
// speedup vs baseline: 1.0267x; 1.0267x over previous
#include <cuda_runtime.h>
#include <cuda_bf16.h>
#include <cstdint>

// ---------------------------------------------------------------------------
// L=256, B=32, D_MODEL=512, N_HEAD=8, D_HEAD=64, 2m=512
// All GEMM-shaped work on mma.sync m16n8k16 bf16; cp.async ping-pong;
// ldmatrix fragment loads. R14 = R12 attn4 (128 regs, 2 CTA/SM) + paired grid.
// Device globals only bound in device code (GB300/ATS pitfall).
// ---------------------------------------------------------------------------
#define ROWS 8192
#define BH 256

__device__ __nv_bfloat16  g_qkvb[ROWS * 2048];       // qkv output bf16
__device__ __nv_bfloat16  g_hb [ROWS * 512];         // h in bf16
__device__ __nv_bfloat16  g_wqkvT[2048 * 512];       // wqkv^T bf16 [N,K]
__device__ __nv_bfloat16  g_woT [512 * 512];         // wo^T bf16 [N,K]
__device__ __nv_bfloat16  g_pT  [256 * 64];          // (C*proj)^T bf16 [m][d]
__device__ __nv_bfloat16  g_qf_b[BH * 256 * 512];    // features bf16
__device__ __nv_bfloat16  g_kf_b[BH * 256 * 512];
__device__ __nv_bfloat16  g_vt [BH * 64 * 256];      // V^T bf16 [bh*64+d][l]
__device__ __nv_bfloat16  g_ai_b[ROWS * 512];        // attn out bf16
__device__ __nv_bfloat16  g_yb [ROWS * 512];         // w_o GEMM result bf16

// ------------------------- helpers ------------------------------------------
__device__ __forceinline__ void mma16816(float c[4],
    uint32_t a0, uint32_t a1, uint32_t a2, uint32_t a3,
    uint32_t b0, uint32_t b1)
{
    asm volatile(
        "mma.sync.aligned.m16n8k16.row.col.f32.bf16.bf16.f32 "
        "{%0,%1,%2,%3}, {%4,%5,%6,%7}, {%8,%9}, {%0,%1,%2,%3};"
        : "+f"(c[0]), "+f"(c[1]), "+f"(c[2]), "+f"(c[3])
        : "r"(a0), "r"(a1), "r"(a2), "r"(a3), "r"(b0), "r"(b1));
}
__device__ __forceinline__ void ldsm4(uint32_t* r, uint32_t addr) {
    asm volatile("ldmatrix.sync.aligned.m8n8.x4.shared.b16 {%0,%1,%2,%3}, [%4];"
        : "=r"(r[0]), "=r"(r[1]), "=r"(r[2]), "=r"(r[3]) : "r"(addr));
}
__device__ __forceinline__ uint32_t pk2(float a, float b) {
    __nv_bfloat162 t = __floats2bfloat162_rn(a, b);
    return *(uint32_t*)&t;
}
__device__ __forceinline__ uint32_t smem_u32(const void* p) {
    uint32_t a;
    asm("{ .reg .u64 t; cvta.to.shared.u64 t, %1; cvt.u32.u64 %0, t; }"
        : "=r"(a) : "l"(p));
    return a;
}
__device__ __forceinline__ void cpa16(uint32_t saddr, const void* g) {
    asm volatile("cp.async.cg.shared.global [%0], [%1], 16;"
                 :: "r"(saddr), "l"(g) : "memory");
}
#define CP_COMMIT() asm volatile("cp.async.commit_group;" ::: "memory")
#define CP_WAIT0()  asm volatile("cp.async.wait_group 0;" ::: "memory")

template<int NW>
__device__ __forceinline__ float block_sum(float v, float* red) {
    #pragma unroll
    for (int o = 16; o; o >>= 1) v += __shfl_xor_sync(0xffffffffu, v, o);
    if ((threadIdx.x & 31) == 0) red[threadIdx.x >> 5] = v;
    __syncthreads();
    if (threadIdx.x < 32) {
        float t = (threadIdx.x < NW) ? red[threadIdx.x] : 0.f;
        #pragma unroll
        for (int o = 16; o; o >>= 1) t += __shfl_xor_sync(0xffffffffu, t, o);
        if (threadIdx.x == 0) red[0] = t;
    }
    __syncthreads();
    float r = red[0];
    __syncthreads();
    return r;
}

// ------------------------- merged prep kernel -------------------------------
__device__ __forceinline__ void transpose_dev(
    const float* __restrict__ src, __nv_bfloat16* __restrict__ dst,
    int K, int N, int bx, int by, int tx, int ty, float (*t)[33])
{
    int bn = bx * 32, bk = by * 32;
    #pragma unroll
    for (int i = ty; i < 32; i += 8)
        t[i][tx] = src[(size_t)(bk + i) * N + bn + tx];
    __syncthreads();
    #pragma unroll
    for (int i = ty; i < 32; i += 8)
        dst[(size_t)(bn + i) * K + bk + tx] = __float2bfloat16(t[tx][i]);
}

__global__ __launch_bounds__(256) void prep_all(
    const float* __restrict__ h, const float* __restrict__ wqkv,
    const float* __restrict__ wo, const float* __restrict__ proj)
{
    __shared__ float tbuf[32][33];
    int blk = blockIdx.x, tid = threadIdx.x;
    int tx = tid & 31, ty = tid >> 5;
    if (blk < 4096) {                       // conv_h
        int i = blk * 256 + tid;
        float4 v = ((const float4*)h)[i];
        struct alignas(8) BF4 { __nv_bfloat162 a, b; };
        BF4 pk;
        pk.a = __floats2bfloat162_rn(v.x, v.y);
        pk.b = __floats2bfloat162_rn(v.z, v.w);
        ((BF4*)g_hb)[i] = pk;
    } else if (blk < 5120) {                // trans_wqkv: 64 x 16
        int idx = blk - 4096;
        transpose_dev(wqkv, g_wqkvT, 512, 2048, idx & 63, idx >> 6, tx, ty, tbuf);
    } else if (blk < 5376) {                // trans_wo: 16 x 16
        int idx = blk - 5120;
        transpose_dev(wo, g_woT, 512, 512, idx & 15, idx >> 4, tx, ty, tbuf);
    } else {                                // prep_pT
        int i = (blk - 5376) * 256 + tid;
        int d = i >> 8, m = i & 255;
        g_pT[m * 64 + d] = __float2bfloat16(proj[i] * 0.3535533905932738f);
    }
}

// ------------------------- bf16 tensor-core GEMM (cp.async + ldmatrix) ------
#define GPAD 36
#define GEMM_SMEM (2 * 9216 * 4)     // 73,728 B

#define GEMM_PREFETCH(p, buf) do {                                             \
    int _b = (buf) * 9216;                                                     \
    _Pragma("unroll")                                                          \
    for (int _j = 0; _j < 4; _j++) {                                           \
        int _i = tid + _j * 256; int _r = _i >> 3, _c = (_i & 7) * 4;          \
        cpa16(sbase + (uint32_t)(_b + _r * GPAD + _c) * 4,                     \
              A32 + (size_t)(bm + _r) * 256 + (p) * 32 + _c);                  \
        cpa16(sbase + (uint32_t)(_b + 4608 + _r * GPAD + _c) * 4,              \
              B32 + (size_t)(bn + _r) * 256 + (p) * 32 + _c);                  \
    }                                                                          \
} while (0)

template<bool BF16OUT>
__device__ __forceinline__ void gemm_body(
    const __nv_bfloat16* __restrict__ A, const __nv_bfloat16* __restrict__ B,
    float* __restrict__ C, uint32_t* __restrict__ Cb, int Ntot)
{
    extern __shared__ uint32_t sw[];
    uint32_t sbase = smem_u32(sw);
    int tid = threadIdx.x, wid = tid >> 5, lane = tid & 31;
    int wm = wid >> 2, wn = wid & 3;
    int g = lane >> 2, t = lane & 3;
    int bm = blockIdx.y * 128, bn = blockIdx.x * 128;
    const uint32_t* A32 = (const uint32_t*)A;
    const uint32_t* B32 = (const uint32_t*)B;

    int arow = wm * 64 + (lane & 15);
    int akof = (lane >> 4) << 2;
    int brow = wn * 32 + ((lane >> 4) & 1) * 8 + (lane & 7);
    int bkof = ((lane >> 3) & 1) << 2;

    float acc[4][4][4];
    #pragma unroll
    for (int i = 0; i < 4; i++)
        #pragma unroll
        for (int j = 0; j < 4; j++)
            #pragma unroll
            for (int q = 0; q < 4; q++) acc[i][j][q] = 0.f;

    GEMM_PREFETCH(0, 0);
    CP_COMMIT();

    for (int p = 0; p < 8; p++) {
        CP_WAIT0();
        __syncthreads();
        if (p < 7) { GEMM_PREFETCH(p + 1, (p + 1) & 1); CP_COMMIT(); }
        uint32_t ab = sbase + (uint32_t)((p & 1) * 9216) * 4;
        uint32_t bb = ab + 4608 * 4;
        #pragma unroll
        for (int kk = 0; kk < 4; kk++) {
            uint32_t af[4][4], bf[2][4];
            #pragma unroll
            for (int i = 0; i < 4; i++)
                ldsm4(af[i], ab + (uint32_t)((arow + i * 16) * GPAD + kk * 8 + akof) * 4);
            #pragma unroll
            for (int jj = 0; jj < 2; jj++)
                ldsm4(bf[jj], bb + (uint32_t)((brow + jj * 16) * GPAD + kk * 8 + bkof) * 4);
            #pragma unroll
            for (int i = 0; i < 4; i++)
                #pragma unroll
                for (int j = 0; j < 4; j++)
                    mma16816(acc[i][j], af[i][0], af[i][1], af[i][2], af[i][3],
                             bf[j >> 1][(j & 1) * 2], bf[j >> 1][(j & 1) * 2 + 1]);
        }
    }
    #pragma unroll
    for (int i = 0; i < 4; i++) {
        int row = bm + wm * 64 + i * 16 + g;
        #pragma unroll
        for (int j = 0; j < 4; j++) {
            if (BF16OUT) {
                int widx = (bn >> 1) + wn * 16 + j * 4 + t;
                Cb[(size_t)row * (Ntot >> 1) + widx] = pk2(acc[i][j][0], acc[i][j][1]);
                Cb[(size_t)(row + 8) * (Ntot >> 1) + widx] = pk2(acc[i][j][2], acc[i][j][3]);
            } else {
                int col = bn + wn * 32 + j * 8 + t * 2;
                *(float2*)&C[(size_t)row * Ntot + col] =
                    make_float2(acc[i][j][0], acc[i][j][1]);
                *(float2*)&C[(size_t)(row + 8) * Ntot + col] =
                    make_float2(acc[i][j][2], acc[i][j][3]);
            }
        }
    }
}
__global__ __launch_bounds__(256) void gemm_qkv() {
    gemm_body<true>(g_hb, g_wqkvT, nullptr, (uint32_t*)g_qkvb, 2048);
}
__global__ __launch_bounds__(256) void gemm_wo() {
    gemm_body<true>(g_ai_b, g_woT, nullptr, (uint32_t*)g_yb, 512);
}

// ------------------------- feat2: FAVOR+ via tensor cores -------------------
#define F_P 0
#define F_X 9216
#define F_V 16128
#define F_STG 18432
#define F_SS 26880
#define FEAT2_SMEM (27392 * 4)     // 109,568 B

__global__ __launch_bounds__(256) void feat2(
    const float* __restrict__ pi0, const float* __restrict__ pi1)
{
    extern __shared__ uint32_t fw[];
    __nv_bfloat16* Vh = (__nv_bfloat16*)(fw + F_V);   // l*72 + d
    float* ss = (float*)(fw + F_SS);
    int tid = threadIdx.x, wid = tid >> 5, lane = tid & 31;
    int wm = wid >> 2, wn = wid & 3;
    int g = lane >> 2, t = lane & 3;
    int l0 = blockIdx.x * 64, bh = blockIdx.y;
    int hh = bh & 7, b = bh >> 3;

    const uint32_t* pTw = (const uint32_t*)g_pT;
    #pragma unroll
    for (int w = 0; w < 32; w++) {
        int idx = tid + w * 256;
        int m = idx >> 5, wd = idx & 31;
        fw[F_P + m * 36 + wd] = pTw[m * 32 + wd];
    }
    const uint32_t* Xg = (const uint32_t*)g_qkvb;
    const __nv_bfloat162 c07 = __float2bfloat162_rn(0.7f);
    #pragma unroll
    for (int w = 0; w < 32; w++) {
        int idx = tid + w * 256;
        int r = idx >> 7, wc = idx & 127;
        uint32_t word = Xg[(size_t)((l0 + r) * 32 + b) * 1024 + hh * 128 + wc];
        if (wc < 96) {
            int seg = wc >> 5, cc = wc & 31;
            if (seg == 2) {
                __nv_bfloat162 tt = *(__nv_bfloat162*)&word;
                tt = __hmul2(tt, c07);
                word = *(uint32_t*)&tt;
            }
            fw[F_X + seg * 2304 + r * 36 + cc] = word;
        } else {
            fw[F_V + r * 36 + (wc - 96)] = word;
        }
    }
    __syncthreads();

    #pragma unroll
    for (int w = 0; w < 16; w++) {
        int idx = tid + w * 256;
        int d = idx >> 6, l = idx & 63;
        g_vt[(size_t)(bh * 64 + d) * 256 + l0 + l] = Vh[l * 72 + d];
    }

    // ===================== seg0: q features =====================
    {
        float acc[2][8][4];
        #pragma unroll
        for (int i = 0; i < 2; i++)
            #pragma unroll
            for (int j = 0; j < 8; j++)
                #pragma unroll
                for (int q = 0; q < 4; q++) acc[i][j][q] = 0.f;
        #pragma unroll
        for (int kk = 0; kk < 4; kk++) {
            uint32_t af[2][4], bf[8][2];
            #pragma unroll
            for (int i = 0; i < 2; i++) {
                int r0 = wm * 32 + i * 16;
                af[i][0] = fw[F_X + (r0 + g    ) * 36 + kk * 8 + t];
                af[i][1] = fw[F_X + (r0 + g + 8) * 36 + kk * 8 + t];
                af[i][2] = fw[F_X + (r0 + g    ) * 36 + kk * 8 + t + 4];
                af[i][3] = fw[F_X + (r0 + g + 8) * 36 + kk * 8 + t + 4];
            }
            #pragma unroll
            for (int j = 0; j < 8; j++) {
                int n0 = wn * 64 + j * 8;
                bf[j][0] = fw[F_P + (n0 + g) * 36 + kk * 8 + t];
                bf[j][1] = fw[F_P + (n0 + g) * 36 + kk * 8 + t + 4];
            }
            #pragma unroll
            for (int i = 0; i < 2; i++)
                #pragma unroll
                for (int j = 0; j < 8; j++)
                    mma16816(acc[i][j], af[i][0], af[i][1], af[i][2], af[i][3],
                             bf[j][0], bf[j][1]);
        }
        float pr[2][2] = {{0.f, 0.f}, {0.f, 0.f}};
        #pragma unroll
        for (int i = 0; i < 2; i++)
            #pragma unroll
            for (int j = 0; j < 8; j++)
                #pragma unroll
                for (int q = 0; q < 4; q++) {
                    float v = fminf(fmaxf(acc[i][j][q], -30.f), 30.f);
                    float e = __expf(v);
                    acc[i][j][q] = e;
                    pr[i][q >> 1] += e + __fdividef(1.f, e);
                }
        #pragma unroll
        for (int i = 0; i < 2; i++)
            #pragma unroll
            for (int hf = 0; hf < 2; hf++) {
                pr[i][hf] += __shfl_xor_sync(0xffffffffu, pr[i][hf], 1);
                pr[i][hf] += __shfl_xor_sync(0xffffffffu, pr[i][hf], 2);
            }
        if (t == 0) {
            #pragma unroll
            for (int i = 0; i < 2; i++) {
                ss[(wm * 32 + i * 16 + g    ) * 4 + wn] = pr[i][0];
                ss[(wm * 32 + i * 16 + g + 8) * 4 + wn] = pr[i][1];
            }
        }
        __syncthreads();
        float invp[2][2];
        #pragma unroll
        for (int i = 0; i < 2; i++)
            #pragma unroll
            for (int hf = 0; hf < 2; hf++) {
                int r = wm * 32 + i * 16 + g + hf * 8;
                float s = ss[r * 4] + ss[r * 4 + 1] + ss[r * 4 + 2] + ss[r * 4 + 3];
                invp[i][hf] = __fdividef(1.f, s);
            }
        uint32_t* dstw = (uint32_t*)g_qf_b;
        #pragma unroll
        for (int i = 0; i < 2; i++) {
            int sr = wm * 32 + i * 16;
            #pragma unroll
            for (int j = 0; j < 8; j++) {
                int wc = wn * 32 + j * 4 + t;
                fw[F_STG + (sr + g    ) * 132 + wc] =
                    pk2(acc[i][j][0] * invp[i][0], acc[i][j][1] * invp[i][0]);
                fw[F_STG + (sr + g + 8) * 132 + wc] =
                    pk2(acc[i][j][2] * invp[i][1], acc[i][j][3] * invp[i][1]);
            }
        }
        __syncthreads();
        #pragma unroll
        for (int w = 0; w < 32; w++) {
            int idx = tid + w * 256;
            int r = idx >> 7, wd = idx & 127;
            dstw[(size_t)(bh * 256 + l0 + r) * 256 + wd] = fw[F_STG + r * 132 + wd];
        }
        __syncthreads();
        #pragma unroll
        for (int i = 0; i < 2; i++) {
            int sr = wm * 32 + i * 16;
            #pragma unroll
            for (int j = 0; j < 8; j++) {
                int wc = wn * 32 + j * 4 + t;
                fw[F_STG + (sr + g    ) * 132 + wc] =
                    pk2(__fdividef(invp[i][0], acc[i][j][0]),
                        __fdividef(invp[i][0], acc[i][j][1]));
                fw[F_STG + (sr + g + 8) * 132 + wc] =
                    pk2(__fdividef(invp[i][1], acc[i][j][2]),
                        __fdividef(invp[i][1], acc[i][j][3]));
            }
        }
        __syncthreads();
        #pragma unroll
        for (int w = 0; w < 32; w++) {
            int idx = tid + w * 256;
            int r = idx >> 7, wd = idx & 127;
            dstw[(size_t)(bh * 256 + l0 + r) * 256 + 128 + wd] = fw[F_STG + r * 132 + wd];
        }
        __syncthreads();
    }

    // ===================== fused seg1+seg2: k features =====================
    {
        float a1[2][8][4], a2[2][8][4];
        #pragma unroll
        for (int i = 0; i < 2; i++)
            #pragma unroll
            for (int j = 0; j < 8; j++)
                #pragma unroll
                for (int q = 0; q < 4; q++) { a1[i][j][q] = 0.f; a2[i][j][q] = 0.f; }
        #pragma unroll
        for (int kk = 0; kk < 4; kk++) {
            uint32_t af1[2][4], af2[2][4], bf[8][2];
            #pragma unroll
            for (int i = 0; i < 2; i++) {
                int r0 = wm * 32 + i * 16;
                af1[i][0] = fw[F_X + 2304 + (r0 + g    ) * 36 + kk * 8 + t];
                af1[i][1] = fw[F_X + 2304 + (r0 + g + 8) * 36 + kk * 8 + t];
                af1[i][2] = fw[F_X + 2304 + (r0 + g    ) * 36 + kk * 8 + t + 4];
                af1[i][3] = fw[F_X + 2304 + (r0 + g + 8) * 36 + kk * 8 + t + 4];
                af2[i][0] = fw[F_X + 4608 + (r0 + g    ) * 36 + kk * 8 + t];
                af2[i][1] = fw[F_X + 4608 + (r0 + g + 8) * 36 + kk * 8 + t];
                af2[i][2] = fw[F_X + 4608 + (r0 + g    ) * 36 + kk * 8 + t + 4];
                af2[i][3] = fw[F_X + 4608 + (r0 + g + 8) * 36 + kk * 8 + t + 4];
            }
            #pragma unroll
            for (int j = 0; j < 8; j++) {
                int n0 = wn * 64 + j * 8;
                bf[j][0] = fw[F_P + (n0 + g) * 36 + kk * 8 + t];
                bf[j][1] = fw[F_P + (n0 + g) * 36 + kk * 8 + t + 4];
            }
            #pragma unroll
            for (int i = 0; i < 2; i++)
                #pragma unroll
                for (int j = 0; j < 8; j++) {
                    mma16816(a1[i][j], af1[i][0], af1[i][1], af1[i][2], af1[i][3],
                             bf[j][0], bf[j][1]);
                    mma16816(a2[i][j], af2[i][0], af2[i][1], af2[i][2], af2[i][3],
                             bf[j][0], bf[j][1]);
                }
        }
        float pr1[2][2] = {{0.f, 0.f}, {0.f, 0.f}};
        float pr2[2][2] = {{0.f, 0.f}, {0.f, 0.f}};
        #pragma unroll
        for (int i = 0; i < 2; i++)
            #pragma unroll
            for (int j = 0; j < 8; j++)
                #pragma unroll
                for (int q = 0; q < 4; q++) {
                    float v1 = fminf(fmaxf(a1[i][j][q], -30.f), 30.f);
                    float e1 = __expf(v1);
                    a1[i][j][q] = e1;
                    pr1[i][q >> 1] += e1 + __fdividef(1.f, e1);
                    float v2 = fminf(fmaxf(a2[i][j][q], -30.f), 30.f);
                    float e2 = __expf(v2);
                    a2[i][j][q] = e2;
                    pr2[i][q >> 1] += e2 + __fdividef(1.f, e2);
                }
        #pragma unroll
        for (int i = 0; i < 2; i++)
            #pragma unroll
            for (int hf = 0; hf < 2; hf++) {
                pr1[i][hf] += __shfl_xor_sync(0xffffffffu, pr1[i][hf], 1);
                pr1[i][hf] += __shfl_xor_sync(0xffffffffu, pr1[i][hf], 2);
                pr2[i][hf] += __shfl_xor_sync(0xffffffffu, pr2[i][hf], 1);
                pr2[i][hf] += __shfl_xor_sync(0xffffffffu, pr2[i][hf], 2);
            }
        if (t == 0) {
            #pragma unroll
            for (int i = 0; i < 2; i++) {
                int ra = wm * 32 + i * 16 + g, rb = ra + 8;
                ss[ra * 4 + wn]       = pr1[i][0];
                ss[rb * 4 + wn]       = pr1[i][1];
                ss[256 + ra * 4 + wn] = pr2[i][0];
                ss[256 + rb * 4 + wn] = pr2[i][1];
            }
        }
        __syncthreads();
        float iv1[2][2], iv2[2][2];
        #pragma unroll
        for (int i = 0; i < 2; i++)
            #pragma unroll
            for (int hf = 0; hf < 2; hf++) {
                int r = wm * 32 + i * 16 + g + hf * 8;
                float s1 = ss[r * 4] + ss[r * 4 + 1] + ss[r * 4 + 2] + ss[r * 4 + 3];
                float s2 = ss[256 + r * 4] + ss[256 + r * 4 + 1]
                         + ss[256 + r * 4 + 2] + ss[256 + r * 4 + 3];
                iv1[i][hf] = __fdividef(pi0[hh * 256 + l0 + r], s1);
                iv2[i][hf] = __fdividef(pi1[hh * 256 + l0 + r], s2);
            }
        uint32_t* dstw = (uint32_t*)g_kf_b;
        #pragma unroll
        for (int i = 0; i < 2; i++) {
            int sr = wm * 32 + i * 16;
            #pragma unroll
            for (int j = 0; j < 8; j++) {
                int wc = wn * 32 + j * 4 + t;
                fw[F_STG + (sr + g    ) * 132 + wc] =
                    pk2(a1[i][j][0] * iv1[i][0] + a2[i][j][0] * iv2[i][0],
                        a1[i][j][1] * iv1[i][0] + a2[i][j][1] * iv2[i][0]);
                fw[F_STG + (sr + g + 8) * 132 + wc] =
                    pk2(a1[i][j][2] * iv1[i][1] + a2[i][j][2] * iv2[i][1],
                        a1[i][j][3] * iv1[i][1] + a2[i][j][3] * iv2[i][1]);
            }
        }
        __syncthreads();
        #pragma unroll
        for (int w = 0; w < 32; w++) {
            int idx = tid + w * 256;
            int r = idx >> 7, wd = idx & 127;
            dstw[(size_t)(bh * 256 + l0 + r) * 256 + wd] = fw[F_STG + r * 132 + wd];
        }
        __syncthreads();
        #pragma unroll
        for (int i = 0; i < 2; i++) {
            int sr = wm * 32 + i * 16;
            #pragma unroll
            for (int j = 0; j < 8; j++) {
                int wc = wn * 32 + j * 4 + t;
                fw[F_STG + (sr + g    ) * 132 + wc] =
                    pk2(__fdividef(iv1[i][0], a1[i][j][0]) + __fdividef(iv2[i][0], a2[i][j][0]),
                        __fdividef(iv1[i][0], a1[i][j][1]) + __fdividef(iv2[i][0], a2[i][j][1]));
                fw[F_STG + (sr + g + 8) * 132 + wc] =
                    pk2(__fdividef(iv1[i][1], a1[i][j][2]) + __fdividef(iv2[i][1], a2[i][j][2]),
                        __fdividef(iv1[i][1], a1[i][j][3]) + __fdividef(iv2[i][1], a2[i][j][3]));
            }
        }
        __syncthreads();
        #pragma unroll
        for (int w = 0; w < 32; w++) {
            int idx = tid + w * 256;
            int r = idx >> 7, wd = idx & 127;
            dstw[(size_t)(bh * 256 + l0 + r) * 256 + 128 + wd] = fw[F_STG + r * 132 + wd];
        }
    }
}

// ------------------------- attn4: R12 structure + paired grid ---------------
// grid (512): bh = blk>>1, tc = 1-(blk&1) (pair adjacency -> K shares L2).
// Single V buffer, V+panel0 at sc-top; ping-pong Q/K; ldmatrix; 128 regs.
#define A4_V 18432
#define A4_D 22784
#define ATTN4_SMEM ((22784 + 128) * 4)    // 91,648 B

#define AT_PREF(p, buf) do {                                                   \
    int _b = (buf) * 9216;                                                      \
    _Pragma("unroll")                                                           \
    for (int _j = 0; _j < 4; _j++) {                                            \
        int _i = tid + _j * 256; int _r = _i >> 3, _c = (_i & 7) * 4;           \
        cpa16(sbase + (uint32_t)(_b + _r * 36 + _c) * 4,                        \
              Qw + (size_t)(bh * 256 + tc * 128 + _r) * 256 + (p) * 32 + _c);   \
        cpa16(sbase + (uint32_t)(_b + 4608 + _r * 36 + _c) * 4,                 \
              Kw + (size_t)(bh * 256 + sc * 128 + _r) * 256 + (p) * 32 + _c);   \
    }                                                                           \
} while (0)

__global__ __launch_bounds__(256, 2) void attn4() {
    extern __shared__ uint32_t aw[];
    uint32_t sbase = smem_u32(aw);
    float* ds = (float*)(aw + A4_D);
    int tid = threadIdx.x, wid = tid >> 5, lane = tid & 31;
    int g = lane >> 2, t = lane & 3;
    int blk = blockIdx.x;
    int bh = blk >> 1;
    int tc = 1 - (blk & 1);
    int hh = bh & 7, b = bh >> 3;
    int lr0 = wid * 16;
    const uint32_t* Qw = (const uint32_t*)g_qf_b;
    const uint32_t* Kw = (const uint32_t*)g_kf_b;
    const uint32_t* Vw = (const uint32_t*)g_vt;

    int alrow = lr0 + (lane & 15);
    int akof  = (lane >> 4) << 2;
    int brow  = ((lane >> 4) & 1) * 8 + (lane & 7);
    int bkof  = ((lane >> 3) & 1) << 2;

    float out[8][4];
    #pragma unroll
    for (int nd = 0; nd < 8; nd++)
        #pragma unroll
        for (int q = 0; q < 4; q++) out[nd][q] = 0.f;
    float dsum0 = 0.f, dsum1 = 0.f;

    for (int sc = 0; sc <= tc; sc++) {
        __syncthreads();
        #pragma unroll
        for (int _j = 0; _j < 4; _j++) {
            int _i = tid + _j * 256;
            int d = _i >> 4, wd = (_i & 15) * 4;
            cpa16(sbase + (uint32_t)(A4_V + d * 68 + wd) * 4,
                  Vw + (size_t)(bh * 64 + d) * 128 + sc * 64 + wd);
        }
        AT_PREF(0, 0);
        CP_COMMIT();

        float acc[16][4];
        #pragma unroll
        for (int j = 0; j < 16; j++)
            #pragma unroll
            for (int q = 0; q < 4; q++) acc[j][q] = 0.f;

        for (int p = 0; p < 8; p++) {
            CP_WAIT0();
            __syncthreads();
            if (p < 7) { AT_PREF(p + 1, (p + 1) & 1); CP_COMMIT(); }
            uint32_t qb = sbase + (uint32_t)((p & 1) * 9216) * 4;
            uint32_t kb = qb + 4608 * 4;
            #pragma unroll
            for (int kk = 0; kk < 4; kk++) {
                uint32_t aq[4];
                ldsm4(aq, qb + (uint32_t)(alrow * 36 + kk * 8 + akof) * 4);
                #pragma unroll
                for (int jj = 0; jj < 8; jj++) {
                    uint32_t bk[4];
                    ldsm4(bk, kb + (uint32_t)((jj * 16 + brow) * 36 + kk * 8 + bkof) * 4);
                    mma16816(acc[2 * jj],     aq[0], aq[1], aq[2], aq[3], bk[0], bk[1]);
                    mma16816(acc[2 * jj + 1], aq[0], aq[1], aq[2], aq[3], bk[2], bk[3]);
                }
            }
        }
        if (sc == tc) {
            int lr = lr0 + g;
            #pragma unroll
            for (int j = 0; j < 16; j++) {
                int c0 = j * 8 + 2 * t;
                if (c0     > lr)     acc[j][0] = 0.f;
                if (c0 + 1 > lr)     acc[j][1] = 0.f;
                if (c0     > lr + 8) acc[j][2] = 0.f;
                if (c0 + 1 > lr + 8) acc[j][3] = 0.f;
            }
        }
        #pragma unroll
        for (int j = 0; j < 16; j++) {
            dsum0 += acc[j][0] + acc[j][1];
            dsum1 += acc[j][2] + acc[j][3];
        }
        #pragma unroll
        for (int ks = 0; ks < 8; ks++) {
            uint32_t a0 = pk2(acc[2 * ks][0],     acc[2 * ks][1]);
            uint32_t a1 = pk2(acc[2 * ks][2],     acc[2 * ks][3]);
            uint32_t a2 = pk2(acc[2 * ks + 1][0], acc[2 * ks + 1][1]);
            uint32_t a3 = pk2(acc[2 * ks + 1][2], acc[2 * ks + 1][3]);
            #pragma unroll
            for (int nd2 = 0; nd2 < 4; nd2++) {
                uint32_t bv[4];
                ldsm4(bv, sbase + (uint32_t)(A4_V + (nd2 * 16 + brow) * 68 + ks * 8 + bkof) * 4);
                mma16816(out[2 * nd2],     a0, a1, a2, a3, bv[0], bv[1]);
                mma16816(out[2 * nd2 + 1], a0, a1, a2, a3, bv[2], bv[3]);
            }
        }
    }

    dsum0 += __shfl_xor_sync(0xffffffffu, dsum0, 1);
    dsum0 += __shfl_xor_sync(0xffffffffu, dsum0, 2);
    dsum1 += __shfl_xor_sync(0xffffffffu, dsum1, 1);
    dsum1 += __shfl_xor_sync(0xffffffffu, dsum1, 2);
    if (t == 0) { ds[lr0 + g] = dsum0; ds[lr0 + g + 8] = dsum1; }
    __syncthreads();
    int r0 = lr0 + g, r1 = lr0 + g + 8;
    float inv0 = __fdividef(0.125f, ds[r0] + 1e-5f);
    float inv1 = __fdividef(0.125f, ds[r1] + 1e-5f);
    int l0g = tc * 128;
    #pragma unroll
    for (int nd = 0; nd < 8; nd++) {
        int d = nd * 8 + 2 * t;
        __nv_bfloat16* d0 = g_ai_b + (size_t)((l0g + r0) * 32 + b) * 512 + hh * 64 + d;
        __nv_bfloat16* d1 = g_ai_b + (size_t)((l0g + r1) * 32 + b) * 512 + hh * 64 + d;
        *(__nv_bfloat162*)d0 = __floats2bfloat162_rn(out[nd][0] * inv0, out[nd][1] * inv0);
        *(__nv_bfloat162*)d1 = __floats2bfloat162_rn(out[nd][2] * inv1, out[nd][3] * inv1);
    }
}

// ------------------------- residual + LayerNorm ----------------------------
__global__ __launch_bounds__(512) void ln_kernel(
    const float* __restrict__ hin, const float* __restrict__ gamma,
    const float* __restrict__ beta, float* __restrict__ out)
{
    __shared__ float red[32];
    int r = blockIdx.x, j = threadIdx.x;
    float x = __bfloat162float(g_yb[(size_t)r * 512 + j]) + hin[(size_t)r * 512 + j];
    float s1 = block_sum<16>(x, red);
    float mu = s1 * (1.f / 512.f);
    float d = x - mu;
    float s2 = block_sum<16>(d * d, red);
    float rstd = rsqrtf(s2 * (1.f / 512.f) + 1e-5f);
    out[(size_t)r * 512 + j] = d * rstd * gamma[j] + beta[j];
}

// ------------------------- launch ------------------------------------------
extern "C" void kernel_launch(void* const* d_in, const int* in_sizes, int n_in,
                              void* d_out, int out_size) {
    const float* h     = (const float*)d_in[0];
    const float* wqkv  = (const float*)d_in[1];
    const float* wo    = (const float*)d_in[2];
    const float* gamma = (const float*)d_in[3];
    const float* beta  = (const float*)d_in[4];
    const float* pi0   = (const float*)d_in[5];
    const float* pi1   = (const float*)d_in[6];
    const float* proj  = (const float*)d_in[7];

    cudaFuncSetAttribute(gemm_qkv, cudaFuncAttributeMaxDynamicSharedMemorySize, GEMM_SMEM);
    cudaFuncSetAttribute(gemm_wo,  cudaFuncAttributeMaxDynamicSharedMemorySize, GEMM_SMEM);
    cudaFuncSetAttribute(feat2,    cudaFuncAttributeMaxDynamicSharedMemorySize, FEAT2_SMEM);
    cudaFuncSetAttribute(attn4,    cudaFuncAttributeMaxDynamicSharedMemorySize, ATTN4_SMEM);

    prep_all<<<5440, 256>>>(h, wqkv, wo, proj);
    gemm_qkv<<<dim3(16, 64), 256, GEMM_SMEM>>>();
    feat2<<<dim3(4, 256), 256, FEAT2_SMEM>>>(pi0, pi1);
    attn4<<<512, 256, ATTN4_SMEM>>>();
    gemm_wo<<<dim3(4, 64), 256, GEMM_SMEM>>>();
    ln_kernel<<<8192, 512>>>(h, gamma, beta, (float*)d_out);
}

// round 15
// speedup vs baseline: 1.1270x; 1.0977x over previous
#include <cuda_runtime.h>
#include <cuda_bf16.h>
#include <cstdint>

// ---------------------------------------------------------------------------
// L=256, B=32, D_MODEL=512, N_HEAD=8, D_HEAD=64, 2m=512
// All GEMM-shaped work on mma.sync m16n8k16 bf16; cp.async ping-pong;
// ldmatrix fragment loads. R15 = R12 attn4 geometry (tc-major (256,2) grid,
// 128 regs, 2 CTA/SM) + warp-per-row LayerNorm.
// Device globals only bound in device code (GB300/ATS pitfall).
// ---------------------------------------------------------------------------
#define ROWS 8192
#define BH 256

__device__ __nv_bfloat16  g_qkvb[ROWS * 2048];       // qkv output bf16
__device__ __nv_bfloat16  g_hb [ROWS * 512];         // h in bf16
__device__ __nv_bfloat16  g_wqkvT[2048 * 512];       // wqkv^T bf16 [N,K]
__device__ __nv_bfloat16  g_woT [512 * 512];         // wo^T bf16 [N,K]
__device__ __nv_bfloat16  g_pT  [256 * 64];          // (C*proj)^T bf16 [m][d]
__device__ __nv_bfloat16  g_qf_b[BH * 256 * 512];    // features bf16
__device__ __nv_bfloat16  g_kf_b[BH * 256 * 512];
__device__ __nv_bfloat16  g_vt [BH * 64 * 256];      // V^T bf16 [bh*64+d][l]
__device__ __nv_bfloat16  g_ai_b[ROWS * 512];        // attn out bf16
__device__ __nv_bfloat16  g_yb [ROWS * 512];         // w_o GEMM result bf16

// ------------------------- helpers ------------------------------------------
__device__ __forceinline__ void mma16816(float c[4],
    uint32_t a0, uint32_t a1, uint32_t a2, uint32_t a3,
    uint32_t b0, uint32_t b1)
{
    asm volatile(
        "mma.sync.aligned.m16n8k16.row.col.f32.bf16.bf16.f32 "
        "{%0,%1,%2,%3}, {%4,%5,%6,%7}, {%8,%9}, {%0,%1,%2,%3};"
        : "+f"(c[0]), "+f"(c[1]), "+f"(c[2]), "+f"(c[3])
        : "r"(a0), "r"(a1), "r"(a2), "r"(a3), "r"(b0), "r"(b1));
}
__device__ __forceinline__ void ldsm4(uint32_t* r, uint32_t addr) {
    asm volatile("ldmatrix.sync.aligned.m8n8.x4.shared.b16 {%0,%1,%2,%3}, [%4];"
        : "=r"(r[0]), "=r"(r[1]), "=r"(r[2]), "=r"(r[3]) : "r"(addr));
}
__device__ __forceinline__ uint32_t pk2(float a, float b) {
    __nv_bfloat162 t = __floats2bfloat162_rn(a, b);
    return *(uint32_t*)&t;
}
__device__ __forceinline__ uint32_t smem_u32(const void* p) {
    uint32_t a;
    asm("{ .reg .u64 t; cvta.to.shared.u64 t, %1; cvt.u32.u64 %0, t; }"
        : "=r"(a) : "l"(p));
    return a;
}
__device__ __forceinline__ void cpa16(uint32_t saddr, const void* g) {
    asm volatile("cp.async.cg.shared.global [%0], [%1], 16;"
                 :: "r"(saddr), "l"(g) : "memory");
}
#define CP_COMMIT() asm volatile("cp.async.commit_group;" ::: "memory")
#define CP_WAIT0()  asm volatile("cp.async.wait_group 0;" ::: "memory")

template<int NW>
__device__ __forceinline__ float block_sum(float v, float* red) {
    #pragma unroll
    for (int o = 16; o; o >>= 1) v += __shfl_xor_sync(0xffffffffu, v, o);
    if ((threadIdx.x & 31) == 0) red[threadIdx.x >> 5] = v;
    __syncthreads();
    if (threadIdx.x < 32) {
        float t = (threadIdx.x < NW) ? red[threadIdx.x] : 0.f;
        #pragma unroll
        for (int o = 16; o; o >>= 1) t += __shfl_xor_sync(0xffffffffu, t, o);
        if (threadIdx.x == 0) red[0] = t;
    }
    __syncthreads();
    float r = red[0];
    __syncthreads();
    return r;
}

// ------------------------- merged prep kernel -------------------------------
__device__ __forceinline__ void transpose_dev(
    const float* __restrict__ src, __nv_bfloat16* __restrict__ dst,
    int K, int N, int bx, int by, int tx, int ty, float (*t)[33])
{
    int bn = bx * 32, bk = by * 32;
    #pragma unroll
    for (int i = ty; i < 32; i += 8)
        t[i][tx] = src[(size_t)(bk + i) * N + bn + tx];
    __syncthreads();
    #pragma unroll
    for (int i = ty; i < 32; i += 8)
        dst[(size_t)(bn + i) * K + bk + tx] = __float2bfloat16(t[tx][i]);
}

__global__ __launch_bounds__(256) void prep_all(
    const float* __restrict__ h, const float* __restrict__ wqkv,
    const float* __restrict__ wo, const float* __restrict__ proj)
{
    __shared__ float tbuf[32][33];
    int blk = blockIdx.x, tid = threadIdx.x;
    int tx = tid & 31, ty = tid >> 5;
    if (blk < 4096) {                       // conv_h
        int i = blk * 256 + tid;
        float4 v = ((const float4*)h)[i];
        struct alignas(8) BF4 { __nv_bfloat162 a, b; };
        BF4 pk;
        pk.a = __floats2bfloat162_rn(v.x, v.y);
        pk.b = __floats2bfloat162_rn(v.z, v.w);
        ((BF4*)g_hb)[i] = pk;
    } else if (blk < 5120) {                // trans_wqkv: 64 x 16
        int idx = blk - 4096;
        transpose_dev(wqkv, g_wqkvT, 512, 2048, idx & 63, idx >> 6, tx, ty, tbuf);
    } else if (blk < 5376) {                // trans_wo: 16 x 16
        int idx = blk - 5120;
        transpose_dev(wo, g_woT, 512, 512, idx & 15, idx >> 4, tx, ty, tbuf);
    } else {                                // prep_pT
        int i = (blk - 5376) * 256 + tid;
        int d = i >> 8, m = i & 255;
        g_pT[m * 64 + d] = __float2bfloat16(proj[i] * 0.3535533905932738f);
    }
}

// ------------------------- bf16 tensor-core GEMM (cp.async + ldmatrix) ------
#define GPAD 36
#define GEMM_SMEM (2 * 9216 * 4)     // 73,728 B

#define GEMM_PREFETCH(p, buf) do {                                             \
    int _b = (buf) * 9216;                                                     \
    _Pragma("unroll")                                                          \
    for (int _j = 0; _j < 4; _j++) {                                           \
        int _i = tid + _j * 256; int _r = _i >> 3, _c = (_i & 7) * 4;          \
        cpa16(sbase + (uint32_t)(_b + _r * GPAD + _c) * 4,                     \
              A32 + (size_t)(bm + _r) * 256 + (p) * 32 + _c);                  \
        cpa16(sbase + (uint32_t)(_b + 4608 + _r * GPAD + _c) * 4,              \
              B32 + (size_t)(bn + _r) * 256 + (p) * 32 + _c);                  \
    }                                                                          \
} while (0)

template<bool BF16OUT>
__device__ __forceinline__ void gemm_body(
    const __nv_bfloat16* __restrict__ A, const __nv_bfloat16* __restrict__ B,
    float* __restrict__ C, uint32_t* __restrict__ Cb, int Ntot)
{
    extern __shared__ uint32_t sw[];
    uint32_t sbase = smem_u32(sw);
    int tid = threadIdx.x, wid = tid >> 5, lane = tid & 31;
    int wm = wid >> 2, wn = wid & 3;
    int g = lane >> 2, t = lane & 3;
    int bm = blockIdx.y * 128, bn = blockIdx.x * 128;
    const uint32_t* A32 = (const uint32_t*)A;
    const uint32_t* B32 = (const uint32_t*)B;

    int arow = wm * 64 + (lane & 15);
    int akof = (lane >> 4) << 2;
    int brow = wn * 32 + ((lane >> 4) & 1) * 8 + (lane & 7);
    int bkof = ((lane >> 3) & 1) << 2;

    float acc[4][4][4];
    #pragma unroll
    for (int i = 0; i < 4; i++)
        #pragma unroll
        for (int j = 0; j < 4; j++)
            #pragma unroll
            for (int q = 0; q < 4; q++) acc[i][j][q] = 0.f;

    GEMM_PREFETCH(0, 0);
    CP_COMMIT();

    for (int p = 0; p < 8; p++) {
        CP_WAIT0();
        __syncthreads();
        if (p < 7) { GEMM_PREFETCH(p + 1, (p + 1) & 1); CP_COMMIT(); }
        uint32_t ab = sbase + (uint32_t)((p & 1) * 9216) * 4;
        uint32_t bb = ab + 4608 * 4;
        #pragma unroll
        for (int kk = 0; kk < 4; kk++) {
            uint32_t af[4][4], bf[2][4];
            #pragma unroll
            for (int i = 0; i < 4; i++)
                ldsm4(af[i], ab + (uint32_t)((arow + i * 16) * GPAD + kk * 8 + akof) * 4);
            #pragma unroll
            for (int jj = 0; jj < 2; jj++)
                ldsm4(bf[jj], bb + (uint32_t)((brow + jj * 16) * GPAD + kk * 8 + bkof) * 4);
            #pragma unroll
            for (int i = 0; i < 4; i++)
                #pragma unroll
                for (int j = 0; j < 4; j++)
                    mma16816(acc[i][j], af[i][0], af[i][1], af[i][2], af[i][3],
                             bf[j >> 1][(j & 1) * 2], bf[j >> 1][(j & 1) * 2 + 1]);
        }
    }
    #pragma unroll
    for (int i = 0; i < 4; i++) {
        int row = bm + wm * 64 + i * 16 + g;
        #pragma unroll
        for (int j = 0; j < 4; j++) {
            if (BF16OUT) {
                int widx = (bn >> 1) + wn * 16 + j * 4 + t;
                Cb[(size_t)row * (Ntot >> 1) + widx] = pk2(acc[i][j][0], acc[i][j][1]);
                Cb[(size_t)(row + 8) * (Ntot >> 1) + widx] = pk2(acc[i][j][2], acc[i][j][3]);
            } else {
                int col = bn + wn * 32 + j * 8 + t * 2;
                *(float2*)&C[(size_t)row * Ntot + col] =
                    make_float2(acc[i][j][0], acc[i][j][1]);
                *(float2*)&C[(size_t)(row + 8) * Ntot + col] =
                    make_float2(acc[i][j][2], acc[i][j][3]);
            }
        }
    }
}
__global__ __launch_bounds__(256) void gemm_qkv() {
    gemm_body<true>(g_hb, g_wqkvT, nullptr, (uint32_t*)g_qkvb, 2048);
}
__global__ __launch_bounds__(256) void gemm_wo() {
    gemm_body<true>(g_ai_b, g_woT, nullptr, (uint32_t*)g_yb, 512);
}

// ------------------------- feat2: FAVOR+ via tensor cores -------------------
#define F_P 0
#define F_X 9216
#define F_V 16128
#define F_STG 18432
#define F_SS 26880
#define FEAT2_SMEM (27392 * 4)     // 109,568 B

__global__ __launch_bounds__(256) void feat2(
    const float* __restrict__ pi0, const float* __restrict__ pi1)
{
    extern __shared__ uint32_t fw[];
    __nv_bfloat16* Vh = (__nv_bfloat16*)(fw + F_V);   // l*72 + d
    float* ss = (float*)(fw + F_SS);
    int tid = threadIdx.x, wid = tid >> 5, lane = tid & 31;
    int wm = wid >> 2, wn = wid & 3;
    int g = lane >> 2, t = lane & 3;
    int l0 = blockIdx.x * 64, bh = blockIdx.y;
    int hh = bh & 7, b = bh >> 3;

    const uint32_t* pTw = (const uint32_t*)g_pT;
    #pragma unroll
    for (int w = 0; w < 32; w++) {
        int idx = tid + w * 256;
        int m = idx >> 5, wd = idx & 31;
        fw[F_P + m * 36 + wd] = pTw[m * 32 + wd];
    }
    const uint32_t* Xg = (const uint32_t*)g_qkvb;
    const __nv_bfloat162 c07 = __float2bfloat162_rn(0.7f);
    #pragma unroll
    for (int w = 0; w < 32; w++) {
        int idx = tid + w * 256;
        int r = idx >> 7, wc = idx & 127;
        uint32_t word = Xg[(size_t)((l0 + r) * 32 + b) * 1024 + hh * 128 + wc];
        if (wc < 96) {
            int seg = wc >> 5, cc = wc & 31;
            if (seg == 2) {
                __nv_bfloat162 tt = *(__nv_bfloat162*)&word;
                tt = __hmul2(tt, c07);
                word = *(uint32_t*)&tt;
            }
            fw[F_X + seg * 2304 + r * 36 + cc] = word;
        } else {
            fw[F_V + r * 36 + (wc - 96)] = word;
        }
    }
    __syncthreads();

    #pragma unroll
    for (int w = 0; w < 16; w++) {
        int idx = tid + w * 256;
        int d = idx >> 6, l = idx & 63;
        g_vt[(size_t)(bh * 64 + d) * 256 + l0 + l] = Vh[l * 72 + d];
    }

    // ===================== seg0: q features =====================
    {
        float acc[2][8][4];
        #pragma unroll
        for (int i = 0; i < 2; i++)
            #pragma unroll
            for (int j = 0; j < 8; j++)
                #pragma unroll
                for (int q = 0; q < 4; q++) acc[i][j][q] = 0.f;
        #pragma unroll
        for (int kk = 0; kk < 4; kk++) {
            uint32_t af[2][4], bf[8][2];
            #pragma unroll
            for (int i = 0; i < 2; i++) {
                int r0 = wm * 32 + i * 16;
                af[i][0] = fw[F_X + (r0 + g    ) * 36 + kk * 8 + t];
                af[i][1] = fw[F_X + (r0 + g + 8) * 36 + kk * 8 + t];
                af[i][2] = fw[F_X + (r0 + g    ) * 36 + kk * 8 + t + 4];
                af[i][3] = fw[F_X + (r0 + g + 8) * 36 + kk * 8 + t + 4];
            }
            #pragma unroll
            for (int j = 0; j < 8; j++) {
                int n0 = wn * 64 + j * 8;
                bf[j][0] = fw[F_P + (n0 + g) * 36 + kk * 8 + t];
                bf[j][1] = fw[F_P + (n0 + g) * 36 + kk * 8 + t + 4];
            }
            #pragma unroll
            for (int i = 0; i < 2; i++)
                #pragma unroll
                for (int j = 0; j < 8; j++)
                    mma16816(acc[i][j], af[i][0], af[i][1], af[i][2], af[i][3],
                             bf[j][0], bf[j][1]);
        }
        float pr[2][2] = {{0.f, 0.f}, {0.f, 0.f}};
        #pragma unroll
        for (int i = 0; i < 2; i++)
            #pragma unroll
            for (int j = 0; j < 8; j++)
                #pragma unroll
                for (int q = 0; q < 4; q++) {
                    float v = fminf(fmaxf(acc[i][j][q], -30.f), 30.f);
                    float e = __expf(v);
                    acc[i][j][q] = e;
                    pr[i][q >> 1] += e + __fdividef(1.f, e);
                }
        #pragma unroll
        for (int i = 0; i < 2; i++)
            #pragma unroll
            for (int hf = 0; hf < 2; hf++) {
                pr[i][hf] += __shfl_xor_sync(0xffffffffu, pr[i][hf], 1);
                pr[i][hf] += __shfl_xor_sync(0xffffffffu, pr[i][hf], 2);
            }
        if (t == 0) {
            #pragma unroll
            for (int i = 0; i < 2; i++) {
                ss[(wm * 32 + i * 16 + g    ) * 4 + wn] = pr[i][0];
                ss[(wm * 32 + i * 16 + g + 8) * 4 + wn] = pr[i][1];
            }
        }
        __syncthreads();
        float invp[2][2];
        #pragma unroll
        for (int i = 0; i < 2; i++)
            #pragma unroll
            for (int hf = 0; hf < 2; hf++) {
                int r = wm * 32 + i * 16 + g + hf * 8;
                float s = ss[r * 4] + ss[r * 4 + 1] + ss[r * 4 + 2] + ss[r * 4 + 3];
                invp[i][hf] = __fdividef(1.f, s);
            }
        uint32_t* dstw = (uint32_t*)g_qf_b;
        #pragma unroll
        for (int i = 0; i < 2; i++) {
            int sr = wm * 32 + i * 16;
            #pragma unroll
            for (int j = 0; j < 8; j++) {
                int wc = wn * 32 + j * 4 + t;
                fw[F_STG + (sr + g    ) * 132 + wc] =
                    pk2(acc[i][j][0] * invp[i][0], acc[i][j][1] * invp[i][0]);
                fw[F_STG + (sr + g + 8) * 132 + wc] =
                    pk2(acc[i][j][2] * invp[i][1], acc[i][j][3] * invp[i][1]);
            }
        }
        __syncthreads();
        #pragma unroll
        for (int w = 0; w < 32; w++) {
            int idx = tid + w * 256;
            int r = idx >> 7, wd = idx & 127;
            dstw[(size_t)(bh * 256 + l0 + r) * 256 + wd] = fw[F_STG + r * 132 + wd];
        }
        __syncthreads();
        #pragma unroll
        for (int i = 0; i < 2; i++) {
            int sr = wm * 32 + i * 16;
            #pragma unroll
            for (int j = 0; j < 8; j++) {
                int wc = wn * 32 + j * 4 + t;
                fw[F_STG + (sr + g    ) * 132 + wc] =
                    pk2(__fdividef(invp[i][0], acc[i][j][0]),
                        __fdividef(invp[i][0], acc[i][j][1]));
                fw[F_STG + (sr + g + 8) * 132 + wc] =
                    pk2(__fdividef(invp[i][1], acc[i][j][2]),
                        __fdividef(invp[i][1], acc[i][j][3]));
            }
        }
        __syncthreads();
        #pragma unroll
        for (int w = 0; w < 32; w++) {
            int idx = tid + w * 256;
            int r = idx >> 7, wd = idx & 127;
            dstw[(size_t)(bh * 256 + l0 + r) * 256 + 128 + wd] = fw[F_STG + r * 132 + wd];
        }
        __syncthreads();
    }

    // ===================== fused seg1+seg2: k features =====================
    {
        float a1[2][8][4], a2[2][8][4];
        #pragma unroll
        for (int i = 0; i < 2; i++)
            #pragma unroll
            for (int j = 0; j < 8; j++)
                #pragma unroll
                for (int q = 0; q < 4; q++) { a1[i][j][q] = 0.f; a2[i][j][q] = 0.f; }
        #pragma unroll
        for (int kk = 0; kk < 4; kk++) {
            uint32_t af1[2][4], af2[2][4], bf[8][2];
            #pragma unroll
            for (int i = 0; i < 2; i++) {
                int r0 = wm * 32 + i * 16;
                af1[i][0] = fw[F_X + 2304 + (r0 + g    ) * 36 + kk * 8 + t];
                af1[i][1] = fw[F_X + 2304 + (r0 + g + 8) * 36 + kk * 8 + t];
                af1[i][2] = fw[F_X + 2304 + (r0 + g    ) * 36 + kk * 8 + t + 4];
                af1[i][3] = fw[F_X + 2304 + (r0 + g + 8) * 36 + kk * 8 + t + 4];
                af2[i][0] = fw[F_X + 4608 + (r0 + g    ) * 36 + kk * 8 + t];
                af2[i][1] = fw[F_X + 4608 + (r0 + g + 8) * 36 + kk * 8 + t];
                af2[i][2] = fw[F_X + 4608 + (r0 + g    ) * 36 + kk * 8 + t + 4];
                af2[i][3] = fw[F_X + 4608 + (r0 + g + 8) * 36 + kk * 8 + t + 4];
            }
            #pragma unroll
            for (int j = 0; j < 8; j++) {
                int n0 = wn * 64 + j * 8;
                bf[j][0] = fw[F_P + (n0 + g) * 36 + kk * 8 + t];
                bf[j][1] = fw[F_P + (n0 + g) * 36 + kk * 8 + t + 4];
            }
            #pragma unroll
            for (int i = 0; i < 2; i++)
                #pragma unroll
                for (int j = 0; j < 8; j++) {
                    mma16816(a1[i][j], af1[i][0], af1[i][1], af1[i][2], af1[i][3],
                             bf[j][0], bf[j][1]);
                    mma16816(a2[i][j], af2[i][0], af2[i][1], af2[i][2], af2[i][3],
                             bf[j][0], bf[j][1]);
                }
        }
        float pr1[2][2] = {{0.f, 0.f}, {0.f, 0.f}};
        float pr2[2][2] = {{0.f, 0.f}, {0.f, 0.f}};
        #pragma unroll
        for (int i = 0; i < 2; i++)
            #pragma unroll
            for (int j = 0; j < 8; j++)
                #pragma unroll
                for (int q = 0; q < 4; q++) {
                    float v1 = fminf(fmaxf(a1[i][j][q], -30.f), 30.f);
                    float e1 = __expf(v1);
                    a1[i][j][q] = e1;
                    pr1[i][q >> 1] += e1 + __fdividef(1.f, e1);
                    float v2 = fminf(fmaxf(a2[i][j][q], -30.f), 30.f);
                    float e2 = __expf(v2);
                    a2[i][j][q] = e2;
                    pr2[i][q >> 1] += e2 + __fdividef(1.f, e2);
                }
        #pragma unroll
        for (int i = 0; i < 2; i++)
            #pragma unroll
            for (int hf = 0; hf < 2; hf++) {
                pr1[i][hf] += __shfl_xor_sync(0xffffffffu, pr1[i][hf], 1);
                pr1[i][hf] += __shfl_xor_sync(0xffffffffu, pr1[i][hf], 2);
                pr2[i][hf] += __shfl_xor_sync(0xffffffffu, pr2[i][hf], 1);
                pr2[i][hf] += __shfl_xor_sync(0xffffffffu, pr2[i][hf], 2);
            }
        if (t == 0) {
            #pragma unroll
            for (int i = 0; i < 2; i++) {
                int ra = wm * 32 + i * 16 + g, rb = ra + 8;
                ss[ra * 4 + wn]       = pr1[i][0];
                ss[rb * 4 + wn]       = pr1[i][1];
                ss[256 + ra * 4 + wn] = pr2[i][0];
                ss[256 + rb * 4 + wn] = pr2[i][1];
            }
        }
        __syncthreads();
        float iv1[2][2], iv2[2][2];
        #pragma unroll
        for (int i = 0; i < 2; i++)
            #pragma unroll
            for (int hf = 0; hf < 2; hf++) {
                int r = wm * 32 + i * 16 + g + hf * 8;
                float s1 = ss[r * 4] + ss[r * 4 + 1] + ss[r * 4 + 2] + ss[r * 4 + 3];
                float s2 = ss[256 + r * 4] + ss[256 + r * 4 + 1]
                         + ss[256 + r * 4 + 2] + ss[256 + r * 4 + 3];
                iv1[i][hf] = __fdividef(pi0[hh * 256 + l0 + r], s1);
                iv2[i][hf] = __fdividef(pi1[hh * 256 + l0 + r], s2);
            }
        uint32_t* dstw = (uint32_t*)g_kf_b;
        #pragma unroll
        for (int i = 0; i < 2; i++) {
            int sr = wm * 32 + i * 16;
            #pragma unroll
            for (int j = 0; j < 8; j++) {
                int wc = wn * 32 + j * 4 + t;
                fw[F_STG + (sr + g    ) * 132 + wc] =
                    pk2(a1[i][j][0] * iv1[i][0] + a2[i][j][0] * iv2[i][0],
                        a1[i][j][1] * iv1[i][0] + a2[i][j][1] * iv2[i][0]);
                fw[F_STG + (sr + g + 8) * 132 + wc] =
                    pk2(a1[i][j][2] * iv1[i][1] + a2[i][j][2] * iv2[i][1],
                        a1[i][j][3] * iv1[i][1] + a2[i][j][3] * iv2[i][1]);
            }
        }
        __syncthreads();
        #pragma unroll
        for (int w = 0; w < 32; w++) {
            int idx = tid + w * 256;
            int r = idx >> 7, wd = idx & 127;
            dstw[(size_t)(bh * 256 + l0 + r) * 256 + wd] = fw[F_STG + r * 132 + wd];
        }
        __syncthreads();
        #pragma unroll
        for (int i = 0; i < 2; i++) {
            int sr = wm * 32 + i * 16;
            #pragma unroll
            for (int j = 0; j < 8; j++) {
                int wc = wn * 32 + j * 4 + t;
                fw[F_STG + (sr + g    ) * 132 + wc] =
                    pk2(__fdividef(iv1[i][0], a1[i][j][0]) + __fdividef(iv2[i][0], a2[i][j][0]),
                        __fdividef(iv1[i][0], a1[i][j][1]) + __fdividef(iv2[i][0], a2[i][j][1]));
                fw[F_STG + (sr + g + 8) * 132 + wc] =
                    pk2(__fdividef(iv1[i][1], a1[i][j][2]) + __fdividef(iv2[i][1], a2[i][j][2]),
                        __fdividef(iv1[i][1], a1[i][j][3]) + __fdividef(iv2[i][1], a2[i][j][3]));
            }
        }
        __syncthreads();
        #pragma unroll
        for (int w = 0; w < 32; w++) {
            int idx = tid + w * 256;
            int r = idx >> 7, wd = idx & 127;
            dstw[(size_t)(bh * 256 + l0 + r) * 256 + 128 + wd] = fw[F_STG + r * 132 + wd];
        }
    }
}

// ------------------------- attn4: R12 geometry (tc-major grid) --------------
// grid (256, 2): blockIdx.y=0 -> all heavy tc=1 blocks launch first.
// Single V buffer, V+panel0 at sc-top; ping-pong Q/K; ldmatrix; 128 regs.
#define A4_V 18432
#define A4_D 22784
#define ATTN4_SMEM ((22784 + 128) * 4)    // 91,648 B

#define AT_PREF(p, buf) do {                                                   \
    int _b = (buf) * 9216;                                                      \
    _Pragma("unroll")                                                           \
    for (int _j = 0; _j < 4; _j++) {                                            \
        int _i = tid + _j * 256; int _r = _i >> 3, _c = (_i & 7) * 4;           \
        cpa16(sbase + (uint32_t)(_b + _r * 36 + _c) * 4,                        \
              Qw + (size_t)(bh * 256 + tc * 128 + _r) * 256 + (p) * 32 + _c);   \
        cpa16(sbase + (uint32_t)(_b + 4608 + _r * 36 + _c) * 4,                 \
              Kw + (size_t)(bh * 256 + sc * 128 + _r) * 256 + (p) * 32 + _c);   \
    }                                                                           \
} while (0)

__global__ __launch_bounds__(256, 2) void attn4() {
    extern __shared__ uint32_t aw[];
    uint32_t sbase = smem_u32(aw);
    float* ds = (float*)(aw + A4_D);
    int tid = threadIdx.x, wid = tid >> 5, lane = tid & 31;
    int g = lane >> 2, t = lane & 3;
    int tc = 1 - (int)blockIdx.y, bh = blockIdx.x;
    int hh = bh & 7, b = bh >> 3;
    int lr0 = wid * 16;
    const uint32_t* Qw = (const uint32_t*)g_qf_b;
    const uint32_t* Kw = (const uint32_t*)g_kf_b;
    const uint32_t* Vw = (const uint32_t*)g_vt;

    int alrow = lr0 + (lane & 15);
    int akof  = (lane >> 4) << 2;
    int brow  = ((lane >> 4) & 1) * 8 + (lane & 7);
    int bkof  = ((lane >> 3) & 1) << 2;

    float out[8][4];
    #pragma unroll
    for (int nd = 0; nd < 8; nd++)
        #pragma unroll
        for (int q = 0; q < 4; q++) out[nd][q] = 0.f;
    float dsum0 = 0.f, dsum1 = 0.f;

    for (int sc = 0; sc <= tc; sc++) {
        __syncthreads();
        #pragma unroll
        for (int _j = 0; _j < 4; _j++) {
            int _i = tid + _j * 256;
            int d = _i >> 4, wd = (_i & 15) * 4;
            cpa16(sbase + (uint32_t)(A4_V + d * 68 + wd) * 4,
                  Vw + (size_t)(bh * 64 + d) * 128 + sc * 64 + wd);
        }
        AT_PREF(0, 0);
        CP_COMMIT();

        float acc[16][4];
        #pragma unroll
        for (int j = 0; j < 16; j++)
            #pragma unroll
            for (int q = 0; q < 4; q++) acc[j][q] = 0.f;

        for (int p = 0; p < 8; p++) {
            CP_WAIT0();
            __syncthreads();
            if (p < 7) { AT_PREF(p + 1, (p + 1) & 1); CP_COMMIT(); }
            uint32_t qb = sbase + (uint32_t)((p & 1) * 9216) * 4;
            uint32_t kb = qb + 4608 * 4;
            #pragma unroll
            for (int kk = 0; kk < 4; kk++) {
                uint32_t aq[4];
                ldsm4(aq, qb + (uint32_t)(alrow * 36 + kk * 8 + akof) * 4);
                #pragma unroll
                for (int jj = 0; jj < 8; jj++) {
                    uint32_t bk[4];
                    ldsm4(bk, kb + (uint32_t)((jj * 16 + brow) * 36 + kk * 8 + bkof) * 4);
                    mma16816(acc[2 * jj],     aq[0], aq[1], aq[2], aq[3], bk[0], bk[1]);
                    mma16816(acc[2 * jj + 1], aq[0], aq[1], aq[2], aq[3], bk[2], bk[3]);
                }
            }
        }
        if (sc == tc) {
            int lr = lr0 + g;
            #pragma unroll
            for (int j = 0; j < 16; j++) {
                int c0 = j * 8 + 2 * t;
                if (c0     > lr)     acc[j][0] = 0.f;
                if (c0 + 1 > lr)     acc[j][1] = 0.f;
                if (c0     > lr + 8) acc[j][2] = 0.f;
                if (c0 + 1 > lr + 8) acc[j][3] = 0.f;
            }
        }
        #pragma unroll
        for (int j = 0; j < 16; j++) {
            dsum0 += acc[j][0] + acc[j][1];
            dsum1 += acc[j][2] + acc[j][3];
        }
        #pragma unroll
        for (int ks = 0; ks < 8; ks++) {
            uint32_t a0 = pk2(acc[2 * ks][0],     acc[2 * ks][1]);
            uint32_t a1 = pk2(acc[2 * ks][2],     acc[2 * ks][3]);
            uint32_t a2 = pk2(acc[2 * ks + 1][0], acc[2 * ks + 1][1]);
            uint32_t a3 = pk2(acc[2 * ks + 1][2], acc[2 * ks + 1][3]);
            #pragma unroll
            for (int nd2 = 0; nd2 < 4; nd2++) {
                uint32_t bv[4];
                ldsm4(bv, sbase + (uint32_t)(A4_V + (nd2 * 16 + brow) * 68 + ks * 8 + bkof) * 4);
                mma16816(out[2 * nd2],     a0, a1, a2, a3, bv[0], bv[1]);
                mma16816(out[2 * nd2 + 1], a0, a1, a2, a3, bv[2], bv[3]);
            }
        }
    }

    dsum0 += __shfl_xor_sync(0xffffffffu, dsum0, 1);
    dsum0 += __shfl_xor_sync(0xffffffffu, dsum0, 2);
    dsum1 += __shfl_xor_sync(0xffffffffu, dsum1, 1);
    dsum1 += __shfl_xor_sync(0xffffffffu, dsum1, 2);
    if (t == 0) { ds[lr0 + g] = dsum0; ds[lr0 + g + 8] = dsum1; }
    __syncthreads();
    int r0 = lr0 + g, r1 = lr0 + g + 8;
    float inv0 = __fdividef(0.125f, ds[r0] + 1e-5f);
    float inv1 = __fdividef(0.125f, ds[r1] + 1e-5f);
    int l0g = tc * 128;
    #pragma unroll
    for (int nd = 0; nd < 8; nd++) {
        int d = nd * 8 + 2 * t;
        __nv_bfloat16* d0 = g_ai_b + (size_t)((l0g + r0) * 32 + b) * 512 + hh * 64 + d;
        __nv_bfloat16* d1 = g_ai_b + (size_t)((l0g + r1) * 32 + b) * 512 + hh * 64 + d;
        *(__nv_bfloat162*)d0 = __floats2bfloat162_rn(out[nd][0] * inv0, out[nd][1] * inv0);
        *(__nv_bfloat162*)d1 = __floats2bfloat162_rn(out[nd][2] * inv1, out[nd][3] * inv1);
    }
}

// ------------------------- residual + LayerNorm (warp-per-row) --------------
// grid 1024, block 256 = 8 warps; each warp owns one row (8 rows per block),
// lane handles 4 columns x 4 strided chunks; pure warp-shuffle reductions.
__global__ __launch_bounds__(256) void ln_kernel(
    const float* __restrict__ hin, const float* __restrict__ gamma,
    const float* __restrict__ beta, float* __restrict__ out)
{
    int warp = threadIdx.x >> 5, lane = threadIdx.x & 31;
    int r = blockIdx.x * 8 + warp;
    const float* hrow = hin + (size_t)r * 512;
    const __nv_bfloat16* yrow = g_yb + (size_t)r * 512;
    float x[16];
    float s = 0.f;
    #pragma unroll
    for (int c = 0; c < 4; c++) {
        int col = c * 128 + lane * 4;
        float4 hv = *(const float4*)(hrow + col);
        uint2 yv = *(const uint2*)(yrow + col);
        __nv_bfloat162 y0 = *(__nv_bfloat162*)&yv.x;
        __nv_bfloat162 y1 = *(__nv_bfloat162*)&yv.y;
        x[c * 4 + 0] = hv.x + __bfloat162float(y0.x);
        x[c * 4 + 1] = hv.y + __bfloat162float(y0.y);
        x[c * 4 + 2] = hv.z + __bfloat162float(y1.x);
        x[c * 4 + 3] = hv.w + __bfloat162float(y1.y);
        s += x[c * 4 + 0] + x[c * 4 + 1] + x[c * 4 + 2] + x[c * 4 + 3];
    }
    #pragma unroll
    for (int o = 16; o; o >>= 1) s += __shfl_xor_sync(0xffffffffu, s, o);
    float mu = s * (1.f / 512.f);
    float v = 0.f;
    #pragma unroll
    for (int q = 0; q < 16; q++) { x[q] -= mu; v += x[q] * x[q]; }
    #pragma unroll
    for (int o = 16; o; o >>= 1) v += __shfl_xor_sync(0xffffffffu, v, o);
    float rstd = rsqrtf(v * (1.f / 512.f) + 1e-5f);
    #pragma unroll
    for (int c = 0; c < 4; c++) {
        int col = c * 128 + lane * 4;
        float4 gv = *(const float4*)(gamma + col);
        float4 bv = *(const float4*)(beta + col);
        float4 ov;
        ov.x = x[c * 4 + 0] * rstd * gv.x + bv.x;
        ov.y = x[c * 4 + 1] * rstd * gv.y + bv.y;
        ov.z = x[c * 4 + 2] * rstd * gv.z + bv.z;
        ov.w = x[c * 4 + 3] * rstd * gv.w + bv.w;
        *(float4*)(out + (size_t)r * 512 + col) = ov;
    }
}

// ------------------------- launch ------------------------------------------
extern "C" void kernel_launch(void* const* d_in, const int* in_sizes, int n_in,
                              void* d_out, int out_size) {
    const float* h     = (const float*)d_in[0];
    const float* wqkv  = (const float*)d_in[1];
    const float* wo    = (const float*)d_in[2];
    const float* gamma = (const float*)d_in[3];
    const float* beta  = (const float*)d_in[4];
    const float* pi0   = (const float*)d_in[5];
    const float* pi1   = (const float*)d_in[6];
    const float* proj  = (const float*)d_in[7];

    cudaFuncSetAttribute(gemm_qkv, cudaFuncAttributeMaxDynamicSharedMemorySize, GEMM_SMEM);
    cudaFuncSetAttribute(gemm_wo,  cudaFuncAttributeMaxDynamicSharedMemorySize, GEMM_SMEM);
    cudaFuncSetAttribute(feat2,    cudaFuncAttributeMaxDynamicSharedMemorySize, FEAT2_SMEM);
    cudaFuncSetAttribute(attn4,    cudaFuncAttributeMaxDynamicSharedMemorySize, ATTN4_SMEM);

    prep_all<<<5440, 256>>>(h, wqkv, wo, proj);
    gemm_qkv<<<dim3(16, 64), 256, GEMM_SMEM>>>();
    feat2<<<dim3(4, 256), 256, FEAT2_SMEM>>>(pi0, pi1);
    attn4<<<dim3(256, 2), 256, ATTN4_SMEM>>>();
    gemm_wo<<<dim3(4, 64), 256, GEMM_SMEM>>>();
    ln_kernel<<<1024, 256>>>(h, gamma, beta, (float*)d_out);
}